// round 7
// baseline (speedup 1.0000x reference)
#include <cuda_runtime.h>
#include <cstdint>

#define NL 32
#define DM 1024
#define NK 4
#define IQO 1024
#define IKV 256
#define IFF 2816

#define MCOLS (IFF / 4)            // 704 float4-columns
#define MQ_TOT (MCOLS * 13)        // 9152 quads of transposed mlp x per layer
#define SMEM_BYTES (MCOLS * 208)   // 146432

// -------- pre-transposed x scratch (prologue kernel) --------
// mlp: quad (l*704 + col)*13 + e*3 + p = x[j=4p..4p+3] at elem col*4+e
// aff: quad (l*cols + col)*5 + e       = x[k=0..3]     at elem col*4+e
__device__ float4 g_xt_mlp[NL * MQ_TOT];
__device__ float4 g_xt_q[NL * 256 * 5];
__device__ float4 g_xt_o[NL * 256 * 5];
__device__ float4 g_xt_k[NL * 64 * 5];
__device__ float4 g_xt_v[NL * 64 * 5];

__global__ void transpose_x_kernel(const float* __restrict__ cq,
                                   const float* __restrict__ ck,
                                   const float* __restrict__ cv,
                                   const float* __restrict__ co,
                                   const float* __restrict__ cm)
{
    const int stride = gridDim.x * blockDim.x;
    const int t0 = blockIdx.x * blockDim.x + threadIdx.x;

    for (int eidx = t0; eidx < NL * IFF; eidx += stride) {
        const int l = eidx / IFF, i = eidx % IFF;
        const int col = i >> 2, e = i & 3;
        const float* src = cm + (size_t)l * 12 * IFF + i;
        float v[12];
        #pragma unroll
        for (int j = 0; j < 12; j++) v[j] = src[(size_t)j * IFF];
        float4* dst = &g_xt_mlp[((size_t)l * MCOLS + col) * 13 + e * 3];
        dst[0] = make_float4(v[0], v[1], v[2], v[3]);
        dst[1] = make_float4(v[4], v[5], v[6], v[7]);
        dst[2] = make_float4(v[8], v[9], v[10], v[11]);
    }
    for (int eidx = t0; eidx < NL * IQO; eidx += stride) {
        const int l = eidx / IQO, i = eidx % IQO;
        const size_t qi = ((size_t)l * 256 + (i >> 2)) * 5 + (i & 3);
        const float* sq = cq + (size_t)l * 4 * IQO + i;
        const float* so = co + (size_t)l * 4 * IQO + i;
        g_xt_q[qi] = make_float4(sq[0], sq[IQO], sq[2 * IQO], sq[3 * IQO]);
        g_xt_o[qi] = make_float4(so[0], so[IQO], so[2 * IQO], so[3 * IQO]);
    }
    for (int eidx = t0; eidx < NL * IKV; eidx += stride) {
        const int l = eidx / IKV, i = eidx % IKV;
        const size_t qi = ((size_t)l * 64 + (i >> 2)) * 5 + (i & 3);
        const float* sk = ck + (size_t)l * 4 * IKV + i;
        const float* sv = cv + (size_t)l * 4 * IKV + i;
        g_xt_k[qi] = make_float4(sk[0], sk[IKV], sk[2 * IKV], sk[3 * IKV]);
        g_xt_v[qi] = make_float4(sv[0], sv[IKV], sv[2 * IKV], sv[3 * IKV]);
    }
}

// -------- PTX helpers --------
__device__ __forceinline__ void ffma2(unsigned long long &d,
                                      unsigned long long a,
                                      unsigned long long b) {
    asm("fma.rn.f32x2 %0, %1, %2, %0;" : "+l"(d) : "l"(a), "l"(b));
}
__device__ __forceinline__ unsigned long long fdup(float f) {
    unsigned long long r;
    asm("mov.b64 %0, {%1, %1};" : "=l"(r) : "f"(f));
    return r;
}
__device__ __forceinline__ void unpack2(unsigned long long v, float &lo, float &hi) {
    asm("mov.b64 {%0, %1}, %2;" : "=f"(lo), "=f"(hi) : "l"(v));
}
__device__ __forceinline__ float getf(float4 v, int e) {
    return (e == 0) ? v.x : (e == 1) ? v.y : (e == 2) ? v.z : v.w;
}
__device__ __forceinline__ float wsum(float v) {
    v += __shfl_xor_sync(0xffffffffu, v, 16);
    v += __shfl_xor_sync(0xffffffffu, v, 8);
    v += __shfl_xor_sync(0xffffffffu, v, 4);
    v += __shfl_xor_sync(0xffffffffu, v, 2);
    v += __shfl_xor_sync(0xffffffffu, v, 1);
    return v;
}
__device__ __forceinline__ void cpasync16(uint32_t dst, const void* src) {
    asm volatile("cp.async.cg.shared.global [%0], [%1], 16;" :: "r"(dst), "l"(src));
}
#define CP_COMMIT() asm volatile("cp.async.commit_group;" ::: "memory")
template <int N>
__device__ __forceinline__ void cp_wait() {
    asm volatile("cp.async.wait_group %0;" :: "n"(N) : "memory");
}
__device__ __forceinline__ void cp_wait_dyn(int n) {
    switch (n) {
        case 0: cp_wait<0>(); break;
        case 1: cp_wait<1>(); break;
        case 2: cp_wait<2>(); break;
        case 3: cp_wait<3>(); break;
        case 4: cp_wait<4>(); break;
        default: cp_wait<5>(); break;
    }
}

// ---- MLP module: 512 thr, 16 warps x 4 rows = 64 rows; 12 RHS share W_down ----
__device__ void mlp_block(const float* __restrict__ Wd,
                          float* __restrict__ out,
                          int l, int dt,
                          char* sm, uint32_t smem_u,
                          int tid, int lane, int wid)
{
    // Stage ALL of this layer's transposed x (9152 quads) in 6 slices.
    // Slice s covers cols [s*128, s*128+128) -> quads [s*1664, +1664) (last 832).
    const float4* xs = g_xt_mlp + (size_t)l * MQ_TOT;
    #pragma unroll
    for (int s = 0; s < 6; s++) {
        const int q0 = s * 1664;
        const int qn = (s < 5) ? 1664 : 832;
        for (int i = tid; i < qn; i += 512)
            cpasync16(smem_u + (q0 + i) * 16, xs + q0 + i);
        CP_COMMIT();
    }

    const float4* w4 = reinterpret_cast<const float4*>(
        Wd + ((size_t)l * DM + dt * 64 + wid * 4) * IFF);

    unsigned long long acc[4][6];
    #pragma unroll
    for (int r = 0; r < 4; r++)
        #pragma unroll
        for (int q = 0; q < 6; q++) acc[r][q] = 0ull;

    // Prefetch first W step (rows are wid*4 .. +3, row stride 704 quads)
    int c = lane;
    float4 nw0 = __ldcs(w4 + 0 * MCOLS + c);
    float4 nw1 = __ldcs(w4 + 1 * MCOLS + c);
    float4 nw2 = __ldcs(w4 + 2 * MCOLS + c);
    float4 nw3 = __ldcs(w4 + 3 * MCOLS + c);

    for (int s = 0; s < 6; s++) {
        cp_wait_dyn(5 - s);
        __syncthreads();
        const int its = (s < 5) ? 4 : 2;
        for (int it = 0; it < its; it++) {
            float4 w0 = nw0, w1 = nw1, w2 = nw2, w3 = nw3;
            const int cn = c + 32;
            if (cn < MCOLS) {
                nw0 = __ldcs(w4 + 0 * MCOLS + cn);
                nw1 = __ldcs(w4 + 1 * MCOLS + cn);
                nw2 = __ldcs(w4 + 2 * MCOLS + cn);
                nw3 = __ldcs(w4 + 3 * MCOLS + cn);
            }
            const char* xp = sm + c * 208;
            #pragma unroll
            for (int e = 0; e < 4; e++) {
                const ulonglong2* xq = reinterpret_cast<const ulonglong2*>(xp + e * 48);
                ulonglong2 p0 = xq[0];
                ulonglong2 p1 = xq[1];
                ulonglong2 p2 = xq[2];
                unsigned long long d0d = fdup(getf(w0, e));
                unsigned long long d1d = fdup(getf(w1, e));
                unsigned long long d2d = fdup(getf(w2, e));
                unsigned long long d3d = fdup(getf(w3, e));
                ffma2(acc[0][0], d0d, p0.x); ffma2(acc[0][1], d0d, p0.y);
                ffma2(acc[0][2], d0d, p1.x); ffma2(acc[0][3], d0d, p1.y);
                ffma2(acc[0][4], d0d, p2.x); ffma2(acc[0][5], d0d, p2.y);
                ffma2(acc[1][0], d1d, p0.x); ffma2(acc[1][1], d1d, p0.y);
                ffma2(acc[1][2], d1d, p1.x); ffma2(acc[1][3], d1d, p1.y);
                ffma2(acc[1][4], d1d, p2.x); ffma2(acc[1][5], d1d, p2.y);
                ffma2(acc[2][0], d2d, p0.x); ffma2(acc[2][1], d2d, p0.y);
                ffma2(acc[2][2], d2d, p1.x); ffma2(acc[2][3], d2d, p1.y);
                ffma2(acc[2][4], d2d, p2.x); ffma2(acc[2][5], d2d, p2.y);
                ffma2(acc[3][0], d3d, p0.x); ffma2(acc[3][1], d3d, p0.y);
                ffma2(acc[3][2], d3d, p1.x); ffma2(acc[3][3], d3d, p1.y);
                ffma2(acc[3][4], d3d, p2.x); ffma2(acc[3][5], d3d, p2.y);
            }
            c = cn;
        }
    }

    // acc[r][q]: lo -> j=2q, hi -> j=2q+1; j=m*4+k; m: 0->gate(3),1->up(4),2->down(6)
    const int d0 = dt * 64 + wid * 4;
    #pragma unroll
    for (int q = 0; q < 6; q++) {
        #pragma unroll
        for (int r = 0; r < 4; r++) {
            float lo, hi;
            unpack2(acc[r][q], lo, hi);
            float vlo = wsum(lo);
            float vhi = wsum(hi);
            #pragma unroll
            for (int h = 0; h < 2; h++) {
                const int j = 2 * q + h;
                const int m = j >> 2;
                const int k = j & 3;
                const int mod = (m == 0) ? 3 : (m == 1) ? 4 : 6;
                const int rowb = (l * 7 + mod) * 8 + 4 + k;
                const float v = h ? vhi : vlo;
                if (lane == ((j * 4 + r) & 31))
                    out[(size_t)rowb * DM + d0 + r] = v;
            }
        }
    }
}

// ---- Affine module (q/k/v/o): 512 thr, 16 warps x 4 rows = 64 rows ----
template <int I>
__device__ void affine_block(const float4* __restrict__ xt,
                             const float* __restrict__ W,
                             float* __restrict__ out,
                             int l, int dt, int mod,
                             char* sm, uint32_t smem_u,
                             int tid, int lane, int wid)
{
    const int COLS = I / 4;
    const float4* xs = xt + (size_t)l * COLS * 5;
    for (int i = tid; i < COLS * 5; i += 512)
        cpasync16(smem_u + i * 16, xs + i);
    CP_COMMIT();

    const float4* w4 = reinterpret_cast<const float4*>(
        W + ((size_t)l * DM + dt * 64 + wid * 4) * I);

    unsigned long long acc[4][2];
    #pragma unroll
    for (int r = 0; r < 4; r++) { acc[r][0] = 0ull; acc[r][1] = 0ull; }

    int c = lane;
    float4 nw0 = __ldcs(w4 + 0 * COLS + c);
    float4 nw1 = __ldcs(w4 + 1 * COLS + c);
    float4 nw2 = __ldcs(w4 + 2 * COLS + c);
    float4 nw3 = __ldcs(w4 + 3 * COLS + c);

    cp_wait<0>();
    __syncthreads();

    #pragma unroll 2
    for (int it = 0; it < COLS / 32; it++) {
        float4 w0 = nw0, w1 = nw1, w2 = nw2, w3 = nw3;
        const int cn = c + 32;
        if (cn < COLS) {
            nw0 = __ldcs(w4 + 0 * COLS + cn);
            nw1 = __ldcs(w4 + 1 * COLS + cn);
            nw2 = __ldcs(w4 + 2 * COLS + cn);
            nw3 = __ldcs(w4 + 3 * COLS + cn);
        }
        const char* xp = sm + c * 80;
        #pragma unroll
        for (int e = 0; e < 4; e++) {
            ulonglong2 xv = *reinterpret_cast<const ulonglong2*>(xp + e * 16);
            unsigned long long d0d = fdup(getf(w0, e));
            unsigned long long d1d = fdup(getf(w1, e));
            unsigned long long d2d = fdup(getf(w2, e));
            unsigned long long d3d = fdup(getf(w3, e));
            ffma2(acc[0][0], d0d, xv.x); ffma2(acc[0][1], d0d, xv.y);
            ffma2(acc[1][0], d1d, xv.x); ffma2(acc[1][1], d1d, xv.y);
            ffma2(acc[2][0], d2d, xv.x); ffma2(acc[2][1], d2d, xv.y);
            ffma2(acc[3][0], d3d, xv.x); ffma2(acc[3][1], d3d, xv.y);
        }
        c = cn;
    }

    const int d0 = dt * 64 + wid * 4;
    const int rowb = (l * 7 + mod) * 8 + 4;
    #pragma unroll
    for (int r = 0; r < 4; r++)
        #pragma unroll
        for (int q = 0; q < 2; q++) {
            float lo, hi;
            unpack2(acc[r][q], lo, hi);
            float vlo = wsum(lo);
            float vhi = wsum(hi);
            const int k0 = 2 * q, k1 = 2 * q + 1;
            if (lane == (r * 4 + k0)) out[(size_t)(rowb + k0) * DM + d0 + r] = vlo;
            if (lane == (r * 4 + k1)) out[(size_t)(rowb + k1) * DM + d0 + r] = vhi;
        }
}

#define NCOPY 64

__global__ __launch_bounds__(512, 1)
void bse_fused_kernel(const float* __restrict__ residual,
                      const float* __restrict__ Wq,
                      const float* __restrict__ Wk,
                      const float* __restrict__ Wv,
                      const float* __restrict__ Wo,
                      const float* __restrict__ Wd,
                      float* __restrict__ out)
{
    extern __shared__ __align__(16) char sm[];
    const int bid = blockIdx.x;
    const int tid = threadIdx.x;
    const int lane = tid & 31;
    const int wid = tid >> 5;
    const uint32_t smem_u = (uint32_t)__cvta_generic_to_shared(sm);

    if (bid < 512) {
        // 16 tiles/layer (64 rows each), longest blocks first
        mlp_block(Wd, out, bid >> 4, bid & 15, sm, smem_u, tid, lane, wid);
    } else if (bid < 1024) {
        const int a = bid - 512;
        affine_block<IQO>(g_xt_q, Wq, out, a >> 4, a & 15, 0, sm, smem_u, tid, lane, wid);
    } else if (bid < 1536) {
        const int a = bid - 1024;
        affine_block<IQO>(g_xt_o, Wo, out, a >> 4, a & 15, 5, sm, smem_u, tid, lane, wid);
    } else if (bid < 1536 + NCOPY) {
        // Residual copy: residual[l,mod,k,:] -> out row (g*8 + k)
        const float4* src = reinterpret_cast<const float4*>(residual);
        float4* dst = reinterpret_cast<float4*>(out);
        const int n = NL * 7 * NK * (DM / 4);          // 229376 float4
        #pragma unroll 4
        for (int e = (bid - 1536) * 512 + tid; e < n; e += NCOPY * 512) {
            const int d = e & 255;
            const int k = (e >> 8) & 3;
            const int g = e >> 10;
            dst[(size_t)(g * 8 + k) * 256 + d] = __ldcs(src + e);
        }
    } else if (bid < 2112 + NCOPY) {
        const int a = bid - (1536 + NCOPY);
        affine_block<IKV>(g_xt_k, Wk, out, a >> 4, a & 15, 1, sm, smem_u, tid, lane, wid);
    } else {
        const int a = bid - (2112 + NCOPY);
        affine_block<IKV>(g_xt_v, Wv, out, a >> 4, a & 15, 2, sm, smem_u, tid, lane, wid);
    }
}

extern "C" void kernel_launch(void* const* d_in, const int* in_sizes, int n_in,
                              void* d_out, int out_size)
{
    (void)in_sizes; (void)n_in; (void)out_size;
    const float* residual = (const float*)d_in[0];
    const float* cq = (const float*)d_in[1];
    const float* ck = (const float*)d_in[2];
    const float* cv = (const float*)d_in[3];
    const float* co = (const float*)d_in[4];
    const float* cm = (const float*)d_in[5];
    const float* Wq = (const float*)d_in[6];
    const float* Wk = (const float*)d_in[7];
    const float* Wv = (const float*)d_in[8];
    const float* Wo = (const float*)d_in[9];
    const float* Wd = (const float*)d_in[10];
    float* out = (float*)d_out;

    static bool attr_done = false;
    if (!attr_done) {
        cudaFuncSetAttribute(bse_fused_kernel,
                             cudaFuncAttributeMaxDynamicSharedMemorySize, SMEM_BYTES);
        attr_done = true;
    }

    transpose_x_kernel<<<352, 256>>>(cq, ck, cv, co, cm);
    bse_fused_kernel<<<2688, 512, SMEM_BYTES>>>(residual,
                                                Wq, Wk, Wv, Wo, Wd, out);
}

// round 8
// speedup vs baseline: 1.0151x; 1.0151x over previous
#include <cuda_runtime.h>
#include <cstdint>

#define NL 32
#define DM 1024
#define NK 4
#define IQO 1024
#define IKV 256
#define IFF 2816
#define HALF (IFF / 2)       // 1408 floats per K-split
#define HCOLS (HALF / 4)     // 352 float4 columns
#define MROW_Q 704           // W_down row stride in quads (IFF/4)

#define SMEM_BYTES (12 * HCOLS * 16)   // 67584 B (MLP x slice); affines use less

// -------- PTX helpers --------
__device__ __forceinline__ float dot4(float4 a, float4 b, float acc) {
    acc = fmaf(a.x, b.x, acc);
    acc = fmaf(a.y, b.y, acc);
    acc = fmaf(a.z, b.z, acc);
    acc = fmaf(a.w, b.w, acc);
    return acc;
}
__device__ __forceinline__ float wsum(float v) {
    v += __shfl_xor_sync(0xffffffffu, v, 16);
    v += __shfl_xor_sync(0xffffffffu, v, 8);
    v += __shfl_xor_sync(0xffffffffu, v, 4);
    v += __shfl_xor_sync(0xffffffffu, v, 2);
    v += __shfl_xor_sync(0xffffffffu, v, 1);
    return v;
}
__device__ __forceinline__ void cpasync16(uint32_t dst, const void* src) {
    asm volatile("cp.async.cg.shared.global [%0], [%1], 16;" :: "r"(dst), "l"(src));
}
#define CP_COMMIT() asm volatile("cp.async.commit_group;" ::: "memory")
__device__ __forceinline__ void cp_wait0() {
    asm volatile("cp.async.wait_group 0;" ::: "memory");
}

// ======== prologue: residual copy + zero-init of MLP-atomic rows ========
__global__ __launch_bounds__(256)
void prologue_kernel(const float4* __restrict__ res, float4* __restrict__ out)
{
    const int n1 = NL * 7 * NK * (DM / 4);   // 229376 residual quads
    const int n2 = NL * 3 * NK * (DM / 4);   // 98304 zero quads (mods 3,4,6)
    const int stride = gridDim.x * blockDim.x;
    const int t0 = blockIdx.x * blockDim.x + threadIdx.x;

    for (int e = t0; e < n1; e += stride) {
        const int d = e & 255;
        const int k = (e >> 8) & 3;
        const int g = e >> 10;                 // l*7 + mod
        out[(size_t)(g * 8 + k) * 256 + d] = __ldcs(res + e);
    }
    const float4 z = make_float4(0.f, 0.f, 0.f, 0.f);
    for (int e = t0; e < n2; e += stride) {
        const int d = e & 255;
        const int k = (e >> 8) & 3;
        const int gm = e >> 10;                // l*3 + mi
        const int l = gm / 3, mi = gm - l * 3;
        const int mod = (mi == 0) ? 3 : (mi == 1) ? 4 : 6;
        out[(size_t)((l * 7 + mod) * 8 + 4 + k) * 256 + d] = z;
    }
}

// ======== MLP module: one K-half per CTA, x fully smem-resident ========
// 256 thr: 8 warps x 4 rows = 32 rows/CTA. Partial sums -> atomicAdd.
__device__ void mlp_block(const float* __restrict__ Wd,
                          const float* __restrict__ cm,
                          float* __restrict__ out,
                          int l, int h, int dt,
                          float4* xs4, uint32_t smem_u,
                          int tid, int lane, int wid)
{
    // Stage x slice: 12 rows x HCOLS quads (4224 quads, 67.6 KB), once.
    const float* xbase = cm + (size_t)l * 12 * IFF + h * HALF;
    #pragma unroll
    for (int s = 0; s < 17; s++) {
        const int i = tid + s * 256;
        if (i < 12 * HCOLS) {
            const int j = i / HCOLS, c = i - j * HCOLS;
            cpasync16(smem_u + i * 16, xbase + (size_t)j * IFF + c * 4);
        }
    }
    CP_COMMIT();

    const int d0 = dt * 32 + wid * 4;
    const float4* w4 = reinterpret_cast<const float4*>(
        Wd + ((size_t)l * DM + d0) * IFF + h * HALF);

    float acc[4][12];
    #pragma unroll
    for (int r = 0; r < 4; r++)
        #pragma unroll
        for (int j = 0; j < 12; j++) acc[r][j] = 0.f;

    // Prefetch first W step while x lands.
    int c = lane;
    float4 nw0 = __ldcs(w4 + 0 * MROW_Q + c);
    float4 nw1 = __ldcs(w4 + 1 * MROW_Q + c);
    float4 nw2 = __ldcs(w4 + 2 * MROW_Q + c);
    float4 nw3 = __ldcs(w4 + 3 * MROW_Q + c);

    cp_wait0();
    __syncthreads();           // the ONLY barrier in this block

    for (int it = 0; it < HCOLS / 32; it++) {      // 11 iterations
        float4 w0 = nw0, w1 = nw1, w2 = nw2, w3 = nw3;
        const int cn = c + 32;
        if (cn < HCOLS) {
            nw0 = __ldcs(w4 + 0 * MROW_Q + cn);
            nw1 = __ldcs(w4 + 1 * MROW_Q + cn);
            nw2 = __ldcs(w4 + 2 * MROW_Q + cn);
            nw3 = __ldcs(w4 + 3 * MROW_Q + cn);
        }
        #pragma unroll
        for (int j = 0; j < 12; j++) {
            float4 xv = xs4[j * HCOLS + c];
            acc[0][j] = dot4(w0, xv, acc[0][j]);
            acc[1][j] = dot4(w1, xv, acc[1][j]);
            acc[2][j] = dot4(w2, xv, acc[2][j]);
            acc[3][j] = dot4(w3, xv, acc[3][j]);
        }
        c = cn;
    }

    // Partial-sum epilogue: atomicAdd into zero-initialized rows.
    // j = m*4 + k ; m: 0->gate(mod 3), 1->up(mod 4), 2->down(mod 6)
    #pragma unroll
    for (int j = 0; j < 12; j++) {
        const int m = j >> 2;
        const int k = j & 3;
        const int mod = (m == 0) ? 3 : (m == 1) ? 4 : 6;
        const int row = (l * 7 + mod) * 8 + 4 + k;
        #pragma unroll
        for (int r = 0; r < 4; r++) {
            float v = wsum(acc[r][j]);
            if (lane == ((j * 4 + r) & 31))
                atomicAdd(&out[(size_t)row * DM + d0 + r], v);
        }
    }
}

// ======== Affine module (q/k/v/o): x smem-resident, direct stores ========
template <int I>
__device__ void affine_block(const float* __restrict__ xg,
                             const float* __restrict__ W,
                             float* __restrict__ out,
                             int l, int dt, int mod,
                             float4* xs4, uint32_t smem_u,
                             int tid, int lane, int wid)
{
    const float4* xg4 = reinterpret_cast<const float4*>(xg) + (size_t)l * I;
    #pragma unroll
    for (int s = 0; s < I / 256; s++) {
        const int i = tid + s * 256;
        cpasync16(smem_u + i * 16, xg4 + i);
    }
    CP_COMMIT();

    const int d0 = dt * 32 + wid * 4;
    const float4* w4 = reinterpret_cast<const float4*>(W) +
                       ((size_t)l * DM + d0) * (I / 4);

    float acc[4][4];
    #pragma unroll
    for (int r = 0; r < 4; r++)
        #pragma unroll
        for (int k = 0; k < 4; k++) acc[r][k] = 0.f;

    int c = lane;
    float4 nw0 = __ldcs(w4 + 0 * (I / 4) + c);
    float4 nw1 = __ldcs(w4 + 1 * (I / 4) + c);
    float4 nw2 = __ldcs(w4 + 2 * (I / 4) + c);
    float4 nw3 = __ldcs(w4 + 3 * (I / 4) + c);

    cp_wait0();
    __syncthreads();

    #pragma unroll 2
    for (int it = 0; it < I / 128; it++) {
        float4 w0 = nw0, w1 = nw1, w2 = nw2, w3 = nw3;
        const int cn = c + 32;
        if (cn < I / 4) {
            nw0 = __ldcs(w4 + 0 * (I / 4) + cn);
            nw1 = __ldcs(w4 + 1 * (I / 4) + cn);
            nw2 = __ldcs(w4 + 2 * (I / 4) + cn);
            nw3 = __ldcs(w4 + 3 * (I / 4) + cn);
        }
        float4 x0 = xs4[0 * (I / 4) + c];
        float4 x1 = xs4[1 * (I / 4) + c];
        float4 x2 = xs4[2 * (I / 4) + c];
        float4 x3 = xs4[3 * (I / 4) + c];
        acc[0][0] = dot4(w0, x0, acc[0][0]);
        acc[0][1] = dot4(w0, x1, acc[0][1]);
        acc[0][2] = dot4(w0, x2, acc[0][2]);
        acc[0][3] = dot4(w0, x3, acc[0][3]);
        acc[1][0] = dot4(w1, x0, acc[1][0]);
        acc[1][1] = dot4(w1, x1, acc[1][1]);
        acc[1][2] = dot4(w1, x2, acc[1][2]);
        acc[1][3] = dot4(w1, x3, acc[1][3]);
        acc[2][0] = dot4(w2, x0, acc[2][0]);
        acc[2][1] = dot4(w2, x1, acc[2][1]);
        acc[2][2] = dot4(w2, x2, acc[2][2]);
        acc[2][3] = dot4(w2, x3, acc[2][3]);
        acc[3][0] = dot4(w3, x0, acc[3][0]);
        acc[3][1] = dot4(w3, x1, acc[3][1]);
        acc[3][2] = dot4(w3, x2, acc[3][2]);
        acc[3][3] = dot4(w3, x3, acc[3][3]);
        c = cn;
    }

    const int rowb = (l * 7 + mod) * 8 + 4;
    #pragma unroll
    for (int r = 0; r < 4; r++)
        #pragma unroll
        for (int k = 0; k < 4; k++) {
            float v = wsum(acc[r][k]);
            if (lane == (r * 4 + k)) out[(size_t)(rowb + k) * DM + d0 + r] = v;
        }
}

// ======== fused main kernel ========
__global__ __launch_bounds__(256, 2)
void bse_fused_kernel(const float* __restrict__ cq,
                      const float* __restrict__ ck,
                      const float* __restrict__ cv,
                      const float* __restrict__ co,
                      const float* __restrict__ cm,
                      const float* __restrict__ Wq,
                      const float* __restrict__ Wk,
                      const float* __restrict__ Wv,
                      const float* __restrict__ Wo,
                      const float* __restrict__ Wd,
                      float* __restrict__ out)
{
    extern __shared__ __align__(16) float4 xs4[];
    const int bid = blockIdx.x;
    const int tid = threadIdx.x;
    const int lane = tid & 31;
    const int wid = tid >> 5;
    const uint32_t smem_u = (uint32_t)__cvta_generic_to_shared(xs4);

    if (bid < 2048) {
        // MLP: l = bid>>6, h = (bid>>5)&1, dt = bid&31
        mlp_block(Wd, cm, out, bid >> 6, (bid >> 5) & 1, bid & 31,
                  xs4, smem_u, tid, lane, wid);
    } else if (bid < 3072) {
        const int a = bid - 2048;
        affine_block<IQO>(cq, Wq, out, a >> 5, a & 31, 0, xs4, smem_u, tid, lane, wid);
    } else if (bid < 4096) {
        const int a = bid - 3072;
        affine_block<IQO>(co, Wo, out, a >> 5, a & 31, 5, xs4, smem_u, tid, lane, wid);
    } else if (bid < 5120) {
        const int a = bid - 4096;
        affine_block<IKV>(ck, Wk, out, a >> 5, a & 31, 1, xs4, smem_u, tid, lane, wid);
    } else {
        const int a = bid - 5120;
        affine_block<IKV>(cv, Wv, out, a >> 5, a & 31, 2, xs4, smem_u, tid, lane, wid);
    }
}

extern "C" void kernel_launch(void* const* d_in, const int* in_sizes, int n_in,
                              void* d_out, int out_size)
{
    (void)in_sizes; (void)n_in; (void)out_size;
    const float* residual = (const float*)d_in[0];
    const float* cq = (const float*)d_in[1];
    const float* ck = (const float*)d_in[2];
    const float* cv = (const float*)d_in[3];
    const float* co = (const float*)d_in[4];
    const float* cm = (const float*)d_in[5];
    const float* Wq = (const float*)d_in[6];
    const float* Wk = (const float*)d_in[7];
    const float* Wv = (const float*)d_in[8];
    const float* Wo = (const float*)d_in[9];
    const float* Wd = (const float*)d_in[10];
    float* out = (float*)d_out;

    static bool attr_done = false;
    if (!attr_done) {
        cudaFuncSetAttribute(bse_fused_kernel,
                             cudaFuncAttributeMaxDynamicSharedMemorySize, SMEM_BYTES);
        attr_done = true;
    }

    prologue_kernel<<<512, 256>>>(reinterpret_cast<const float4*>(residual),
                                  reinterpret_cast<float4*>(out));
    bse_fused_kernel<<<6144, 256, SMEM_BYTES>>>(cq, ck, cv, co, cm,
                                                Wq, Wk, Wv, Wo, Wd, out);
}

// round 9
// speedup vs baseline: 1.2085x; 1.1906x over previous
#include <cuda_runtime.h>

#define NL 32
#define DM 1024
#define NK 4
#define IQO 1024
#define IKV 256
#define IFF 2816

// Output row layout: row = (l*7 + mod)*8 + s*4 + k, columns = DM.
// MODULE_ORDER = [q, k, v, gate, up, o, down] -> mod 0..6.

__device__ __forceinline__ float dot4(float4 a, float4 b, float acc) {
    acc = fmaf(a.x, b.x, acc);
    acc = fmaf(a.y, b.y, acc);
    acc = fmaf(a.z, b.z, acc);
    acc = fmaf(a.w, b.w, acc);
    return acc;
}

__device__ __forceinline__ float wsum(float v) {
    v += __shfl_xor_sync(0xffffffffu, v, 16);
    v += __shfl_xor_sync(0xffffffffu, v, 8);
    v += __shfl_xor_sync(0xffffffffu, v, 4);
    v += __shfl_xor_sync(0xffffffffu, v, 2);
    v += __shfl_xor_sync(0xffffffffu, v, 1);
    return v;
}

// ---- Affine module (q/k/v/o): proj[k,d] = sum_i x[k,i] * W[d,i], K=4 RHS ----
template <int I>
__device__ void affine_block(const float* __restrict__ xg,
                             const float* __restrict__ W,
                             float* __restrict__ out,
                             int l, int dt, int mod,
                             float4* xs4, int tid, int lane, int wid)
{
    // Stage x[4][I] into smem: 4*I floats = I float4.
    const float4* xg4 = reinterpret_cast<const float4*>(xg) + (size_t)l * I;
    #pragma unroll
    for (int i = tid; i < I; i += 256) xs4[i] = xg4[i];
    __syncthreads();

    const int d0 = dt * 32 + wid * 4;
    const float4* w4 = reinterpret_cast<const float4*>(W) + ((size_t)l * DM + d0) * (I / 4);

    float acc[4][4];
    #pragma unroll
    for (int r = 0; r < 4; r++)
        #pragma unroll
        for (int k = 0; k < 4; k++) acc[r][k] = 0.f;

    #pragma unroll 2
    for (int c = lane; c < I / 4; c += 32) {
        float4 x0 = xs4[c];
        float4 x1 = xs4[(I / 4) + c];
        float4 x2 = xs4[2 * (I / 4) + c];
        float4 x3 = xs4[3 * (I / 4) + c];
        #pragma unroll
        for (int r = 0; r < 4; r++) {
            float4 w = __ldcs(w4 + r * (I / 4) + c);
            acc[r][0] = dot4(w, x0, acc[r][0]);
            acc[r][1] = dot4(w, x1, acc[r][1]);
            acc[r][2] = dot4(w, x2, acc[r][2]);
            acc[r][3] = dot4(w, x3, acc[r][3]);
        }
    }

    const int rowb = (l * 7 + mod) * 8 + 4;
    #pragma unroll
    for (int r = 0; r < 4; r++)
        #pragma unroll
        for (int k = 0; k < 4; k++) {
            float v = wsum(acc[r][k]);
            if (lane == (r * 4 + k)) out[(size_t)(rowb + k) * DM + d0 + r] = v;
        }
}

// ---- MLP module: 3 modules (gate/up/down) share W_down -> 12 accumulators ----
__device__ void mlp_block(const float* __restrict__ cm,
                          const float* __restrict__ Wd,
                          float* __restrict__ out,
                          int l, int dt,
                          float4* xs4, int tid, int lane, int wid)
{
    const int d0 = dt * 32 + wid * 4;
    const float4* xg4 = reinterpret_cast<const float4*>(cm) + (size_t)l * 3 * NK * (IFF / 4);
    const float4* w4  = reinterpret_cast<const float4*>(Wd) + ((size_t)l * DM + d0) * (IFF / 4);

    float acc[4][12];
    #pragma unroll
    for (int r = 0; r < 4; r++)
        #pragma unroll
        for (int j = 0; j < 12; j++) acc[r][j] = 0.f;

    // Staging: 12 rows x 256 floats per chunk = 768 float4; thread t stages
    // rows j0, j0+4, j0+8 at column i0.
    const int j0 = tid >> 6;
    const int i0 = tid & 63;
    const int base = j0 * (IFF / 4) + i0;

    float4 pre0 = xg4[base];
    float4 pre1 = xg4[base + 4 * (IFF / 4)];
    float4 pre2 = xg4[base + 8 * (IFF / 4)];

    for (int c = 0; c < 11; ++c) {
        __syncthreads();                 // previous chunk fully consumed
        xs4[tid]       = pre0;
        xs4[tid + 256] = pre1;
        xs4[tid + 512] = pre2;
        __syncthreads();
        if (c < 10) {
            pre0 = xg4[base + (c + 1) * 64];
            pre1 = xg4[base + 4 * (IFF / 4) + (c + 1) * 64];
            pre2 = xg4[base + 8 * (IFF / 4) + (c + 1) * 64];
        }
        #pragma unroll
        for (int it = 0; it < 2; ++it) {
            const int cc = it * 32 + lane;
            const int wc = c * 64 + cc;
            float4 w0 = __ldcs(w4 + 0 * (IFF / 4) + wc);
            float4 w1 = __ldcs(w4 + 1 * (IFF / 4) + wc);
            float4 w2 = __ldcs(w4 + 2 * (IFF / 4) + wc);
            float4 w3 = __ldcs(w4 + 3 * (IFF / 4) + wc);
            #pragma unroll
            for (int j = 0; j < 12; j++) {
                float4 xv = xs4[j * 64 + cc];
                acc[0][j] = dot4(w0, xv, acc[0][j]);
                acc[1][j] = dot4(w1, xv, acc[1][j]);
                acc[2][j] = dot4(w2, xv, acc[2][j]);
                acc[3][j] = dot4(w3, xv, acc[3][j]);
            }
        }
    }

    // j = m*4 + k ; m=0 -> gate (mod 3), m=1 -> up (mod 4), m=2 -> down (mod 6)
    #pragma unroll
    for (int j = 0; j < 12; j++) {
        const int m = j >> 2;
        const int k = j & 3;
        const int mod = (m == 0) ? 3 : (m == 1) ? 4 : 6;
        const int rowb = (l * 7 + mod) * 8 + 4 + k;
        #pragma unroll
        for (int r = 0; r < 4; r++) {
            float v = wsum(acc[r][j]);
            if (lane == ((j * 4 + r) & 31)) out[(size_t)rowb * DM + d0 + r] = v;
        }
    }
}

// Roles
#define R_MLP 0
#define R_Q   1
#define R_O   2
#define R_K   3
#define R_V   4
#define R_CP  5

__global__ __launch_bounds__(256, 2)
void bse_fused_kernel(const float* __restrict__ residual,
                      const float* __restrict__ cq,
                      const float* __restrict__ ck,
                      const float* __restrict__ cv,
                      const float* __restrict__ co,
                      const float* __restrict__ cm,
                      const float* __restrict__ Wq,
                      const float* __restrict__ Wk,
                      const float* __restrict__ Wv,
                      const float* __restrict__ Wo,
                      const float* __restrict__ Wd,
                      float* __restrict__ out)
{
    __shared__ float4 xs4[1024];   // 16 KB
    const int bid = blockIdx.x;
    const int tid = threadIdx.x;
    const int lane = tid & 31;
    const int wid = tid >> 5;

    // ---- heterogeneous pairing dispatch ----
    // Classic placement maps bid -> SM via (bid % 148): bids b and b+148
    // co-reside. Alternate 148-block brigades of MLP (fma-dense) and QO
    // (mem-dense) so each SM holds one of each.
    int role, id;
    if (bid < 2072) {                       // 14 brigades of 148
        const int g = bid / 148;
        const int r = bid - g * 148;
        const int half = (g >> 1) * 148 + r;     // 0..1035
        if ((g & 1) == 0) {
            if (half < 1024) { role = R_MLP; id = half; }
            else             { role = R_CP;  id = half - 1024; }   // 12 ids
        } else {
            if (half < 1024) { role = R_Q;   id = half; }
            else             { role = R_O;   id = half - 1024; }   // 12 ids
        }
    } else {
        const int t = bid - 2072;                // 0..3559
        if (t < 1012)       { role = R_O;  id = 12 + t; }
        else if (t < 2036)  { role = R_K;  id = t - 1012; }
        else if (t < 3060)  { role = R_V;  id = t - 2036; }
        else                { role = R_CP; id = 12 + (t - 3060); } // 12..511
    }

    if (role == R_MLP) {
        mlp_block(cm, Wd, out, id >> 5, id & 31, xs4, tid, lane, wid);
    } else if (role == R_Q) {
        affine_block<IQO>(cq, Wq, out, id >> 5, id & 31, 0, xs4, tid, lane, wid);
    } else if (role == R_O) {
        affine_block<IQO>(co, Wo, out, id >> 5, id & 31, 5, xs4, tid, lane, wid);
    } else if (role == R_K) {
        affine_block<IKV>(ck, Wk, out, id >> 5, id & 31, 1, xs4, tid, lane, wid);
    } else if (role == R_V) {
        affine_block<IKV>(cv, Wv, out, id >> 5, id & 31, 2, xs4, tid, lane, wid);
    } else {
        // Residual copy: residual[l,mod,k,:] -> out row (g*8 + k)
        const float4* src = reinterpret_cast<const float4*>(residual);
        float4* dst = reinterpret_cast<float4*>(out);
        const int n = NL * 7 * NK * (DM / 4);          // 229376 float4
        for (int e = id * 256 + tid; e < n; e += 512 * 256) {
            const int d = e & 255;
            const int k = (e >> 8) & 3;
            const int g = e >> 10;
            dst[(size_t)(g * 8 + k) * 256 + d] = __ldcs(src + e);
        }
    }
}

extern "C" void kernel_launch(void* const* d_in, const int* in_sizes, int n_in,
                              void* d_out, int out_size)
{
    (void)in_sizes; (void)n_in; (void)out_size;
    const float* residual = (const float*)d_in[0];
    const float* cq = (const float*)d_in[1];
    const float* ck = (const float*)d_in[2];
    const float* cv = (const float*)d_in[3];
    const float* co = (const float*)d_in[4];
    const float* cm = (const float*)d_in[5];
    const float* Wq = (const float*)d_in[6];
    const float* Wk = (const float*)d_in[7];
    const float* Wv = (const float*)d_in[8];
    const float* Wo = (const float*)d_in[9];
    const float* Wd = (const float*)d_in[10];
    float* out = (float*)d_out;

    bse_fused_kernel<<<5632, 256>>>(residual, cq, ck, cv, co, cm,
                                    Wq, Wk, Wv, Wo, Wd, out);
}

// round 10
// speedup vs baseline: 1.2659x; 1.0474x over previous
#include <cuda_runtime.h>
#include <cstdint>

#define NL 32
#define DM 1024
#define NK 4
#define IQO 1024
#define IKV 256
#define IFF 2816
#define MQ (IFF / 4)                 // 704 f4 cols

#define XBUF_BYTES 24576             // MLP x double buffer: 2 x 768 quads
#define WRING_OFF  24576
#define WRING_WARP 10240             // 5 slots x 2048 B
#define SMEM_BYTES (WRING_OFF + 8 * WRING_WARP)   // 106496

// Output row layout: row = (l*7 + mod)*8 + s*4 + k, columns = DM.
// MODULE_ORDER = [q, k, v, gate, up, o, down] -> mod 0..6.

__device__ __forceinline__ float dot4(float4 a, float4 b, float acc) {
    acc = fmaf(a.x, b.x, acc);
    acc = fmaf(a.y, b.y, acc);
    acc = fmaf(a.z, b.z, acc);
    acc = fmaf(a.w, b.w, acc);
    return acc;
}
__device__ __forceinline__ float wsum(float v) {
    v += __shfl_xor_sync(0xffffffffu, v, 16);
    v += __shfl_xor_sync(0xffffffffu, v, 8);
    v += __shfl_xor_sync(0xffffffffu, v, 4);
    v += __shfl_xor_sync(0xffffffffu, v, 2);
    v += __shfl_xor_sync(0xffffffffu, v, 1);
    return v;
}
__device__ __forceinline__ void cpasync16(uint32_t dst, const void* src) {
    asm volatile("cp.async.cg.shared.global [%0], [%1], 16;" :: "r"(dst), "l"(src));
}
#define CP_COMMIT() asm volatile("cp.async.commit_group;" ::: "memory")
__device__ __forceinline__ void cp_wait3() {
    asm volatile("cp.async.wait_group 3;" ::: "memory");
}

// ---- MLP module: gate/up/down share W_down -> 12 accumulators ----
// 256 thr, 8 warps x 4 rows. W via per-warp 5-slot cp.async ring (22 steps).
__device__ void mlp_block(const float* __restrict__ cm,
                          const float* __restrict__ Wd,
                          float* __restrict__ out,
                          int l, int dt,
                          char* sm, uint32_t smem_u,
                          int tid, int lane, int wid)
{
    const int d0 = dt * 32 + wid * 4;
    const float4* xg4 = reinterpret_cast<const float4*>(cm) + (size_t)l * 3 * NK * MQ;
    const float* wbase = Wd + ((size_t)l * DM + d0) * IFF;
    float4* xbuf = reinterpret_cast<float4*>(sm);
    const uint32_t wring_u = smem_u + WRING_OFF + wid * WRING_WARP;
    const char* wring = sm + WRING_OFF + wid * WRING_WARP;

    // Issue W step s (32 f4 cols x 4 rows = 2 KB) into ring slot s%5.
    auto wstep = [&](int s) {
        if (s < 22) {
            const uint32_t dst = wring_u + (s % 5) * 2048 + lane * 16;
            const float* src = wbase + s * 128 + lane * 4;
            #pragma unroll
            for (int q = 0; q < 4; q++)
                cpasync16(dst + q * 512, src + (size_t)q * IFF);
        }
        CP_COMMIT();
    };

    // x prefetch (chunk 0): thread stages rows j0, j0+4, j0+8 at col i0.
    const int j0 = tid >> 6;
    const int i0 = tid & 63;
    const int xb0 = j0 * MQ + i0;
    float4 pre0 = xg4[xb0];
    float4 pre1 = xg4[xb0 + 4 * MQ];
    float4 pre2 = xg4[xb0 + 8 * MQ];

    wstep(0); wstep(1); wstep(2); wstep(3);

    float acc[4][12];
    #pragma unroll
    for (int r = 0; r < 4; r++)
        #pragma unroll
        for (int j = 0; j < 12; j++) acc[r][j] = 0.f;

    for (int c = 0; c < 11; ++c) {
        float4* xb = xbuf + (c & 1) * 768;
        xb[tid]       = pre0;
        xb[tid + 256] = pre1;
        xb[tid + 512] = pre2;
        __syncthreads();                       // one barrier per chunk
        if (c < 10) {
            pre0 = xg4[xb0 + (c + 1) * 64];
            pre1 = xg4[xb0 + 4 * MQ + (c + 1) * 64];
            pre2 = xg4[xb0 + 8 * MQ + (c + 1) * 64];
        }
        #pragma unroll
        for (int it = 0; it < 2; ++it) {
            const int step = c * 2 + it;
            cp_wait3();                        // per-warp: step's slot ready
            const float4* wq = reinterpret_cast<const float4*>(
                wring + (step % 5) * 2048);
            float4 w0 = wq[lane];
            float4 w1 = wq[32 + lane];
            float4 w2 = wq[64 + lane];
            float4 w3 = wq[96 + lane];
            wstep(step + 4);
            const int cc = it * 32 + lane;
            #pragma unroll
            for (int j = 0; j < 12; j++) {
                float4 xv = xb[j * 64 + cc];
                acc[0][j] = dot4(w0, xv, acc[0][j]);
                acc[1][j] = dot4(w1, xv, acc[1][j]);
                acc[2][j] = dot4(w2, xv, acc[2][j]);
                acc[3][j] = dot4(w3, xv, acc[3][j]);
            }
        }
    }

    // j = m*4 + k ; m=0 -> gate (mod 3), m=1 -> up (mod 4), m=2 -> down (mod 6)
    #pragma unroll
    for (int j = 0; j < 12; j++) {
        const int m = j >> 2;
        const int k = j & 3;
        const int mod = (m == 0) ? 3 : (m == 1) ? 4 : 6;
        const int rowb = (l * 7 + mod) * 8 + 4 + k;
        #pragma unroll
        for (int r = 0; r < 4; r++) {
            float v = wsum(acc[r][j]);
            if (lane == ((j * 4 + r) & 31)) out[(size_t)rowb * DM + d0 + r] = v;
        }
    }
}

// ---- Affine module (q/k/v/o): 4 RHS; same per-warp W ring ----
template <int I>
__device__ void affine_block(const float* __restrict__ xg,
                             const float* __restrict__ W,
                             float* __restrict__ out,
                             int l, int dt, int mod,
                             char* sm, uint32_t smem_u,
                             int tid, int lane, int wid)
{
    const int COLS = I / 4;
    const int S = COLS / 32;                  // 8 (IQO) or 2 (IKV)
    const int d0 = dt * 32 + wid * 4;
    const float* wbase = W + ((size_t)l * DM + d0) * I;
    float4* xs4 = reinterpret_cast<float4*>(sm);
    const uint32_t wring_u = smem_u + WRING_OFF + wid * WRING_WARP;
    const char* wring = sm + WRING_OFF + wid * WRING_WARP;

    auto wstep = [&](int s) {
        if (s < S) {
            const uint32_t dst = wring_u + (s % 5) * 2048 + lane * 16;
            const float* src = wbase + s * 128 + lane * 4;
            #pragma unroll
            for (int q = 0; q < 4; q++)
                cpasync16(dst + q * 512, src + (size_t)q * I);
        }
        CP_COMMIT();
    };

    wstep(0); wstep(1); wstep(2); wstep(3);

    // Stage x[4][I] into smem (I quads).
    const float4* xg4 = reinterpret_cast<const float4*>(xg) + (size_t)l * I;
    #pragma unroll
    for (int i = tid; i < I; i += 256) xs4[i] = xg4[i];
    __syncthreads();

    float acc[4][4];
    #pragma unroll
    for (int r = 0; r < 4; r++)
        #pragma unroll
        for (int k = 0; k < 4; k++) acc[r][k] = 0.f;

    for (int s = 0; s < S; ++s) {
        cp_wait3();
        const float4* wq = reinterpret_cast<const float4*>(wring + (s % 5) * 2048);
        float4 w0 = wq[lane];
        float4 w1 = wq[32 + lane];
        float4 w2 = wq[64 + lane];
        float4 w3 = wq[96 + lane];
        wstep(s + 4);
        const int c = s * 32 + lane;
        float4 x0 = xs4[c];
        float4 x1 = xs4[COLS + c];
        float4 x2 = xs4[2 * COLS + c];
        float4 x3 = xs4[3 * COLS + c];
        acc[0][0] = dot4(w0, x0, acc[0][0]);
        acc[0][1] = dot4(w0, x1, acc[0][1]);
        acc[0][2] = dot4(w0, x2, acc[0][2]);
        acc[0][3] = dot4(w0, x3, acc[0][3]);
        acc[1][0] = dot4(w1, x0, acc[1][0]);
        acc[1][1] = dot4(w1, x1, acc[1][1]);
        acc[1][2] = dot4(w1, x2, acc[1][2]);
        acc[1][3] = dot4(w1, x3, acc[1][3]);
        acc[2][0] = dot4(w2, x0, acc[2][0]);
        acc[2][1] = dot4(w2, x1, acc[2][1]);
        acc[2][2] = dot4(w2, x2, acc[2][2]);
        acc[2][3] = dot4(w2, x3, acc[2][3]);
        acc[3][0] = dot4(w3, x0, acc[3][0]);
        acc[3][1] = dot4(w3, x1, acc[3][1]);
        acc[3][2] = dot4(w3, x2, acc[3][2]);
        acc[3][3] = dot4(w3, x3, acc[3][3]);
    }

    const int rowb = (l * 7 + mod) * 8 + 4;
    #pragma unroll
    for (int r = 0; r < 4; r++)
        #pragma unroll
        for (int k = 0; k < 4; k++) {
            float v = wsum(acc[r][k]);
            if (lane == (r * 4 + k)) out[(size_t)(rowb + k) * DM + d0 + r] = v;
        }
}

__global__ __launch_bounds__(256, 2)
void bse_fused_kernel(const float* __restrict__ residual,
                      const float* __restrict__ cq,
                      const float* __restrict__ ck,
                      const float* __restrict__ cv,
                      const float* __restrict__ co,
                      const float* __restrict__ cm,
                      const float* __restrict__ Wq,
                      const float* __restrict__ Wk,
                      const float* __restrict__ Wv,
                      const float* __restrict__ Wo,
                      const float* __restrict__ Wd,
                      float* __restrict__ out)
{
    extern __shared__ __align__(16) char sm[];
    const int bid = blockIdx.x;
    const int tid = threadIdx.x;
    const int lane = tid & 31;
    const int wid = tid >> 5;
    const uint32_t smem_u = (uint32_t)__cvta_generic_to_shared(sm);

    if (bid < 1024) {
        mlp_block(cm, Wd, out, bid >> 5, bid & 31, sm, smem_u, tid, lane, wid);
    } else if (bid < 2048) {
        const int a = bid - 1024;
        affine_block<IQO>(cq, Wq, out, a >> 5, a & 31, 0, sm, smem_u, tid, lane, wid);
    } else if (bid < 3072) {
        const int a = bid - 2048;
        affine_block<IQO>(co, Wo, out, a >> 5, a & 31, 5, sm, smem_u, tid, lane, wid);
    } else if (bid < 4096) {
        const int a = bid - 3072;
        affine_block<IKV>(ck, Wk, out, a >> 5, a & 31, 1, sm, smem_u, tid, lane, wid);
    } else if (bid < 5120) {
        const int a = bid - 4096;
        affine_block<IKV>(cv, Wv, out, a >> 5, a & 31, 2, sm, smem_u, tid, lane, wid);
    } else {
        // Residual copy: residual[l,mod,k,:] -> out row (g*8 + k)
        const float4* src = reinterpret_cast<const float4*>(residual);
        float4* dst = reinterpret_cast<float4*>(out);
        const int n = NL * 7 * NK * (DM / 4);          // 229376 float4
        for (int e = (bid - 5120) * 256 + tid; e < n; e += 512 * 256) {
            const int d = e & 255;
            const int k = (e >> 8) & 3;
            const int g = e >> 10;
            dst[(size_t)(g * 8 + k) * 256 + d] = __ldcs(src + e);
        }
    }
}

extern "C" void kernel_launch(void* const* d_in, const int* in_sizes, int n_in,
                              void* d_out, int out_size)
{
    (void)in_sizes; (void)n_in; (void)out_size;
    const float* residual = (const float*)d_in[0];
    const float* cq = (const float*)d_in[1];
    const float* ck = (const float*)d_in[2];
    const float* cv = (const float*)d_in[3];
    const float* co = (const float*)d_in[4];
    const float* cm = (const float*)d_in[5];
    const float* Wq = (const float*)d_in[6];
    const float* Wk = (const float*)d_in[7];
    const float* Wv = (const float*)d_in[8];
    const float* Wo = (const float*)d_in[9];
    const float* Wd = (const float*)d_in[10];
    float* out = (float*)d_out;

    static bool attr_done = false;
    if (!attr_done) {
        cudaFuncSetAttribute(bse_fused_kernel,
                             cudaFuncAttributeMaxDynamicSharedMemorySize, SMEM_BYTES);
        attr_done = true;
    }

    bse_fused_kernel<<<5632, 256, SMEM_BYTES>>>(residual, cq, ck, cv, co, cm,
                                                Wq, Wk, Wv, Wo, Wd, out);
}

// round 11
// speedup vs baseline: 1.3691x; 1.0815x over previous
#include <cuda_runtime.h>
#include <cstdint>

#define NL 32
#define DM 1024
#define NK 4
#define IQO 1024
#define IKV 256
#define IFF 2816
#define MQ (IFF / 4)                  // 704 f4 cols

#define XCHUNK_B 13312                // 64 cols x 13 quads x 16 B (12 used + 1 pad)
#define XBUF_B (2 * XCHUNK_B)         // 26624
#define WRING_OFF XBUF_B
#define WRING_WARP 10240              // 5 slots x 2048 B
#define SMEM_BYTES (WRING_OFF + 8 * WRING_WARP)   // 108544

// -------- packed-RHS transposed MLP x (prologue) --------
// quad (l*IFF + i)*3 + p = x[j=4p..4p+3] at element i
__device__ float4 g_xt_mlp[NL * IFF * 3];

__global__ void transpose_x_kernel(const float* __restrict__ cm)
{
    const int stride = gridDim.x * blockDim.x;
    for (int e = blockIdx.x * blockDim.x + threadIdx.x; e < NL * IFF; e += stride) {
        const int l = e / IFF, i = e % IFF;
        const float* src = cm + (size_t)l * 12 * IFF + i;
        float v[12];
        #pragma unroll
        for (int j = 0; j < 12; j++) v[j] = src[(size_t)j * IFF];
        float4* dst = &g_xt_mlp[(size_t)e * 3];
        dst[0] = make_float4(v[0], v[1], v[2], v[3]);
        dst[1] = make_float4(v[4], v[5], v[6], v[7]);
        dst[2] = make_float4(v[8], v[9], v[10], v[11]);
    }
}

// -------- helpers --------
__device__ __forceinline__ float dot4(float4 a, float4 b, float acc) {
    acc = fmaf(a.x, b.x, acc);
    acc = fmaf(a.y, b.y, acc);
    acc = fmaf(a.z, b.z, acc);
    acc = fmaf(a.w, b.w, acc);
    return acc;
}
__device__ __forceinline__ void ffma2(unsigned long long &d,
                                      unsigned long long a,
                                      unsigned long long b) {
    asm("fma.rn.f32x2 %0, %1, %2, %0;" : "+l"(d) : "l"(a), "l"(b));
}
__device__ __forceinline__ unsigned long long fdup(float f) {
    unsigned long long r;
    asm("mov.b64 %0, {%1, %1};" : "=l"(r) : "f"(f));
    return r;
}
__device__ __forceinline__ void unpack2(unsigned long long v, float &lo, float &hi) {
    asm("mov.b64 {%0, %1}, %2;" : "=f"(lo), "=f"(hi) : "l"(v));
}
__device__ __forceinline__ float getf(float4 v, int e) {
    return (e == 0) ? v.x : (e == 1) ? v.y : (e == 2) ? v.z : v.w;
}
__device__ __forceinline__ float wsum(float v) {
    v += __shfl_xor_sync(0xffffffffu, v, 16);
    v += __shfl_xor_sync(0xffffffffu, v, 8);
    v += __shfl_xor_sync(0xffffffffu, v, 4);
    v += __shfl_xor_sync(0xffffffffu, v, 2);
    v += __shfl_xor_sync(0xffffffffu, v, 1);
    return v;
}
__device__ __forceinline__ float hsum16(float v) {
    v += __shfl_xor_sync(0xffffffffu, v, 8);
    v += __shfl_xor_sync(0xffffffffu, v, 4);
    v += __shfl_xor_sync(0xffffffffu, v, 2);
    v += __shfl_xor_sync(0xffffffffu, v, 1);
    return v;
}
__device__ __forceinline__ void cpasync16(uint32_t dst, const void* src) {
    asm volatile("cp.async.cg.shared.global [%0], [%1], 16;" :: "r"(dst), "l"(src));
}
#define CP_COMMIT() asm volatile("cp.async.commit_group;" ::: "memory")
__device__ __forceinline__ void cp_wait3() {
    asm volatile("cp.async.wait_group 3;" ::: "memory");
}

// ---- MLP module: 8 warps x 8 rows = 64 rows/CTA; 12 RHS packed FFMA2 ----
__device__ void mlp_block(const float* __restrict__ Wd,
                          float* __restrict__ out,
                          int l, int dt,
                          char* sm, uint32_t smem_u,
                          int tid, int lane, int wid)
{
    const int rh = lane >> 4;            // row half 0/1
    const int col = lane & 15;           // column within step
    const float* wbase = Wd + ((size_t)l * DM + dt * 64 + wid * 8) * IFF;
    const uint32_t wring_u = smem_u + WRING_OFF + wid * WRING_WARP;
    const char* wring = sm + WRING_OFF + wid * WRING_WARP;
    const float4* xg4 = g_xt_mlp + (size_t)l * IFF * 3;

    // W ring step s (s=0..43): 16 f4-cols x 8 rows = 2 KB into slot s%5.
    auto wstep = [&](int s) {
        if (s < 44) {
            const uint32_t dst = wring_u + (s % 5) * 2048 + (rh * 64 + col) * 16;
            const float* src = wbase + (size_t)(rh * 4) * IFF + (s * 16 + col) * 4;
            #pragma unroll
            for (int q = 0; q < 4; q++)
                cpasync16(dst + q * 256, src + (size_t)q * IFF);
        }
        CP_COMMIT();
    };

    // x staging: thread stages 3 quads/chunk to padded 13-quad col blocks.
    int sdst[3];
    float4 pre[3];
    #pragma unroll
    for (int k = 0; k < 3; k++) {
        const int lq = tid + k * 256;
        sdst[k] = (lq / 12) * 13 + (lq % 12);
        pre[k] = xg4[lq];
    }

    wstep(0); wstep(1); wstep(2); wstep(3);

    unsigned long long acc[4][6];
    #pragma unroll
    for (int q = 0; q < 4; q++)
        #pragma unroll
        for (int p = 0; p < 6; p++) acc[q][p] = 0ull;

    for (int c = 0; c < 11; ++c) {
        float4* xb = reinterpret_cast<float4*>(sm + (c & 1) * XCHUNK_B);
        #pragma unroll
        for (int k = 0; k < 3; k++) xb[sdst[k]] = pre[k];
        __syncthreads();
        if (c < 10) {
            #pragma unroll
            for (int k = 0; k < 3; k++) pre[k] = xg4[(c + 1) * 768 + tid + k * 256];
        }
        #pragma unroll
        for (int it = 0; it < 4; ++it) {
            const int s = c * 4 + it;
            cp_wait3();
            const char* wq = wring + (s % 5) * 2048;
            float4 w0 = *reinterpret_cast<const float4*>(wq + (rh * 64 + 0 * 16 + col) * 16);
            float4 w1 = *reinterpret_cast<const float4*>(wq + (rh * 64 + 1 * 16 + col) * 16);
            float4 w2 = *reinterpret_cast<const float4*>(wq + (rh * 64 + 2 * 16 + col) * 16);
            float4 w3 = *reinterpret_cast<const float4*>(wq + (rh * 64 + 3 * 16 + col) * 16);
            wstep(s + 4);
            const char* xp = reinterpret_cast<const char*>(xb) + (it * 16 + col) * 208;
            #pragma unroll
            for (int e = 0; e < 4; e++) {
                const ulonglong2* xq = reinterpret_cast<const ulonglong2*>(xp + e * 48);
                ulonglong2 x0 = xq[0];
                ulonglong2 x1 = xq[1];
                ulonglong2 x2 = xq[2];
                unsigned long long d0 = fdup(getf(w0, e));
                unsigned long long d1 = fdup(getf(w1, e));
                unsigned long long d2 = fdup(getf(w2, e));
                unsigned long long d3 = fdup(getf(w3, e));
                ffma2(acc[0][0], d0, x0.x); ffma2(acc[0][1], d0, x0.y);
                ffma2(acc[0][2], d0, x1.x); ffma2(acc[0][3], d0, x1.y);
                ffma2(acc[0][4], d0, x2.x); ffma2(acc[0][5], d0, x2.y);
                ffma2(acc[1][0], d1, x0.x); ffma2(acc[1][1], d1, x0.y);
                ffma2(acc[1][2], d1, x1.x); ffma2(acc[1][3], d1, x1.y);
                ffma2(acc[1][4], d1, x2.x); ffma2(acc[1][5], d1, x2.y);
                ffma2(acc[2][0], d2, x0.x); ffma2(acc[2][1], d2, x0.y);
                ffma2(acc[2][2], d2, x1.x); ffma2(acc[2][3], d2, x1.y);
                ffma2(acc[2][4], d2, x2.x); ffma2(acc[2][5], d2, x2.y);
                ffma2(acc[3][0], d3, x0.x); ffma2(acc[3][1], d3, x0.y);
                ffma2(acc[3][2], d3, x1.x); ffma2(acc[3][3], d3, x1.y);
                ffma2(acc[3][4], d3, x2.x); ffma2(acc[3][5], d3, x2.y);
            }
        }
    }

    // Reduce over the 16 lanes of each row-half; acc[q][pp]: lo->j=2pp, hi->2pp+1.
    // d = dt*64 + wid*8 + rh*4 + q. j=m*4+k; m: 0->gate(3), 1->up(4), 2->down(6).
    const int d0w = dt * 64 + wid * 8 + rh * 4;
    const int li = lane & 15;
    #pragma unroll
    for (int q = 0; q < 4; q++)
        #pragma unroll
        for (int pp = 0; pp < 6; pp++) {
            float lo, hi;
            unpack2(acc[q][pp], lo, hi);
            lo = hsum16(lo);
            hi = hsum16(hi);
            if (li == ((q * 6 + pp) & 15)) {
                #pragma unroll
                for (int h = 0; h < 2; h++) {
                    const int j = 2 * pp + h;
                    const int m = j >> 2;
                    const int k = j & 3;
                    const int mod = (m == 0) ? 3 : (m == 1) ? 4 : 6;
                    out[(size_t)((l * 7 + mod) * 8 + 4 + k) * DM + d0w + q] =
                        h ? hi : lo;
                }
            }
        }
}

// ---- Affine module (q/k/v/o): R10-identical (4 rows/warp, W rings) ----
template <int I>
__device__ void affine_block(const float* __restrict__ xg,
                             const float* __restrict__ W,
                             float* __restrict__ out,
                             int l, int dt, int mod,
                             char* sm, uint32_t smem_u,
                             int tid, int lane, int wid)
{
    const int COLS = I / 4;
    const int S = COLS / 32;
    const int d0 = dt * 32 + wid * 4;
    const float* wbase = W + ((size_t)l * DM + d0) * I;
    float4* xs4 = reinterpret_cast<float4*>(sm);
    const uint32_t wring_u = smem_u + WRING_OFF + wid * WRING_WARP;
    const char* wring = sm + WRING_OFF + wid * WRING_WARP;

    auto wstep = [&](int s) {
        if (s < S) {
            const uint32_t dst = wring_u + (s % 5) * 2048 + lane * 16;
            const float* src = wbase + s * 128 + lane * 4;
            #pragma unroll
            for (int q = 0; q < 4; q++)
                cpasync16(dst + q * 512, src + (size_t)q * I);
        }
        CP_COMMIT();
    };

    wstep(0); wstep(1); wstep(2); wstep(3);

    const float4* xg4 = reinterpret_cast<const float4*>(xg) + (size_t)l * I;
    #pragma unroll
    for (int i = tid; i < I; i += 256) xs4[i] = xg4[i];
    __syncthreads();

    float acc[4][4];
    #pragma unroll
    for (int r = 0; r < 4; r++)
        #pragma unroll
        for (int k = 0; k < 4; k++) acc[r][k] = 0.f;

    for (int s = 0; s < S; ++s) {
        cp_wait3();
        const float4* wq = reinterpret_cast<const float4*>(wring + (s % 5) * 2048);
        float4 w0 = wq[lane];
        float4 w1 = wq[32 + lane];
        float4 w2 = wq[64 + lane];
        float4 w3 = wq[96 + lane];
        wstep(s + 4);
        const int c = s * 32 + lane;
        float4 x0 = xs4[c];
        float4 x1 = xs4[COLS + c];
        float4 x2 = xs4[2 * COLS + c];
        float4 x3 = xs4[3 * COLS + c];
        acc[0][0] = dot4(w0, x0, acc[0][0]);
        acc[0][1] = dot4(w0, x1, acc[0][1]);
        acc[0][2] = dot4(w0, x2, acc[0][2]);
        acc[0][3] = dot4(w0, x3, acc[0][3]);
        acc[1][0] = dot4(w1, x0, acc[1][0]);
        acc[1][1] = dot4(w1, x1, acc[1][1]);
        acc[1][2] = dot4(w1, x2, acc[1][2]);
        acc[1][3] = dot4(w1, x3, acc[1][3]);
        acc[2][0] = dot4(w2, x0, acc[2][0]);
        acc[2][1] = dot4(w2, x1, acc[2][1]);
        acc[2][2] = dot4(w2, x2, acc[2][2]);
        acc[2][3] = dot4(w2, x3, acc[2][3]);
        acc[3][0] = dot4(w3, x0, acc[3][0]);
        acc[3][1] = dot4(w3, x1, acc[3][1]);
        acc[3][2] = dot4(w3, x2, acc[3][2]);
        acc[3][3] = dot4(w3, x3, acc[3][3]);
    }

    const int rowb = (l * 7 + mod) * 8 + 4;
    #pragma unroll
    for (int r = 0; r < 4; r++)
        #pragma unroll
        for (int k = 0; k < 4; k++) {
            float v = wsum(acc[r][k]);
            if (lane == (r * 4 + k)) out[(size_t)(rowb + k) * DM + d0 + r] = v;
        }
}

__global__ __launch_bounds__(256, 2)
void bse_fused_kernel(const float* __restrict__ residual,
                      const float* __restrict__ cq,
                      const float* __restrict__ ck,
                      const float* __restrict__ cv,
                      const float* __restrict__ co,
                      const float* __restrict__ cm,
                      const float* __restrict__ Wq,
                      const float* __restrict__ Wk,
                      const float* __restrict__ Wv,
                      const float* __restrict__ Wo,
                      const float* __restrict__ Wd,
                      float* __restrict__ out)
{
    extern __shared__ __align__(16) char sm[];
    const int bid = blockIdx.x;
    const int tid = threadIdx.x;
    const int lane = tid & 31;
    const int wid = tid >> 5;
    const uint32_t smem_u = (uint32_t)__cvta_generic_to_shared(sm);
    (void)cm;

    if (bid < 512) {
        mlp_block(Wd, out, bid >> 4, bid & 15, sm, smem_u, tid, lane, wid);
    } else if (bid < 1536) {
        const int a = bid - 512;
        affine_block<IQO>(cq, Wq, out, a >> 5, a & 31, 0, sm, smem_u, tid, lane, wid);
    } else if (bid < 2560) {
        const int a = bid - 1536;
        affine_block<IQO>(co, Wo, out, a >> 5, a & 31, 5, sm, smem_u, tid, lane, wid);
    } else if (bid < 3584) {
        const int a = bid - 2560;
        affine_block<IKV>(ck, Wk, out, a >> 5, a & 31, 1, sm, smem_u, tid, lane, wid);
    } else if (bid < 4608) {
        const int a = bid - 3584;
        affine_block<IKV>(cv, Wv, out, a >> 5, a & 31, 2, sm, smem_u, tid, lane, wid);
    } else {
        // Residual copy: residual[l,mod,k,:] -> out row (g*8 + k)
        const float4* src = reinterpret_cast<const float4*>(residual);
        float4* dst = reinterpret_cast<float4*>(out);
        const int n = NL * 7 * NK * (DM / 4);          // 229376 float4
        for (int e = (bid - 4608) * 256 + tid; e < n; e += 512 * 256) {
            const int d = e & 255;
            const int k = (e >> 8) & 3;
            const int g = e >> 10;
            dst[(size_t)(g * 8 + k) * 256 + d] = __ldcs(src + e);
        }
    }
}

extern "C" void kernel_launch(void* const* d_in, const int* in_sizes, int n_in,
                              void* d_out, int out_size)
{
    (void)in_sizes; (void)n_in; (void)out_size;
    const float* residual = (const float*)d_in[0];
    const float* cq = (const float*)d_in[1];
    const float* ck = (const float*)d_in[2];
    const float* cv = (const float*)d_in[3];
    const float* co = (const float*)d_in[4];
    const float* cm = (const float*)d_in[5];
    const float* Wq = (const float*)d_in[6];
    const float* Wk = (const float*)d_in[7];
    const float* Wv = (const float*)d_in[8];
    const float* Wo = (const float*)d_in[9];
    const float* Wd = (const float*)d_in[10];
    float* out = (float*)d_out;

    static bool attr_done = false;
    if (!attr_done) {
        cudaFuncSetAttribute(bse_fused_kernel,
                             cudaFuncAttributeMaxDynamicSharedMemorySize, SMEM_BYTES);
        attr_done = true;
    }

    transpose_x_kernel<<<256, 256>>>(cm);
    bse_fused_kernel<<<5120, 256, SMEM_BYTES>>>(residual, cq, ck, cv, co, cm,
                                                Wq, Wk, Wv, Wo, Wd, out);
}

// round 12
// speedup vs baseline: 1.3716x; 1.0019x over previous
#include <cuda_runtime.h>
#include <cstdint>

#define NL 32
#define DM 1024
#define NK 4
#define IQO 1024
#define IKV 256
#define IFF 2816

#define XCHUNK_B 12288                // 768 quads, e-major: ((e*3+p)*64 + cc)*16
#define WRING_OFF (2 * XCHUNK_B)      // 24576
#define WRING_WARP 10240              // 5 slots x 2048 B
#define SMEM_BYTES (WRING_OFF + 8 * WRING_WARP)   // 106496

// -------- transposed x scratch (prologue) --------
// mlp: quad (l*11 + c)*768 + (e*3+p)*64 + ccl   = x[j=4p..4p+3] at elem ((c*64+ccl)*4+e)
// q/o: quad l*1024 + e*256 + cc                 = x[k=0..3] at elem cc*4+e
// k/v: quad l*256  + e*64  + cc
__device__ float4 g_xt_mlp[NL * 11 * 768];
__device__ float4 g_xt_q[NL * 1024];
__device__ float4 g_xt_o[NL * 1024];
__device__ float4 g_xt_k[NL * 256];
__device__ float4 g_xt_v[NL * 256];

__global__ void transpose_x_kernel(const float* __restrict__ cq,
                                   const float* __restrict__ ck,
                                   const float* __restrict__ cv,
                                   const float* __restrict__ co,
                                   const float* __restrict__ cm)
{
    const int stride = gridDim.x * blockDim.x;
    const int t0 = blockIdx.x * blockDim.x + threadIdx.x;

    for (int e = t0; e < NL * IFF; e += stride) {
        const int l = e / IFF, i = e % IFF;
        const int cc = i >> 2, ee = i & 3;
        const int c = cc >> 6, ccl = cc & 63;
        const float* src = cm + (size_t)l * 12 * IFF + i;
        float v[12];
        #pragma unroll
        for (int j = 0; j < 12; j++) v[j] = src[(size_t)j * IFF];
        float4* dst = g_xt_mlp + (size_t)(l * 11 + c) * 768 + ee * 192 + ccl;
        dst[0]   = make_float4(v[0], v[1], v[2], v[3]);
        dst[64]  = make_float4(v[4], v[5], v[6], v[7]);
        dst[128] = make_float4(v[8], v[9], v[10], v[11]);
    }
    for (int e = t0; e < NL * IQO; e += stride) {
        const int l = e / IQO, i = e % IQO;
        const int cc = i >> 2, ee = i & 3;
        const float* sq = cq + (size_t)l * 4 * IQO + i;
        const float* so = co + (size_t)l * 4 * IQO + i;
        const size_t qi = (size_t)l * 1024 + ee * 256 + cc;
        g_xt_q[qi] = make_float4(sq[0], sq[IQO], sq[2 * IQO], sq[3 * IQO]);
        g_xt_o[qi] = make_float4(so[0], so[IQO], so[2 * IQO], so[3 * IQO]);
    }
    for (int e = t0; e < NL * IKV; e += stride) {
        const int l = e / IKV, i = e % IKV;
        const int cc = i >> 2, ee = i & 3;
        const float* sk = ck + (size_t)l * 4 * IKV + i;
        const float* sv = cv + (size_t)l * 4 * IKV + i;
        const size_t qi = (size_t)l * 256 + ee * 64 + cc;
        g_xt_k[qi] = make_float4(sk[0], sk[IKV], sk[2 * IKV], sk[3 * IKV]);
        g_xt_v[qi] = make_float4(sv[0], sv[IKV], sv[2 * IKV], sv[3 * IKV]);
    }
}

// -------- helpers --------
__device__ __forceinline__ void ffma2(unsigned long long &d,
                                      unsigned long long a,
                                      unsigned long long b) {
    asm("fma.rn.f32x2 %0, %1, %2, %0;" : "+l"(d) : "l"(a), "l"(b));
}
__device__ __forceinline__ unsigned long long fdup(float f) {
    unsigned long long r;
    asm("mov.b64 %0, {%1, %1};" : "=l"(r) : "f"(f));
    return r;
}
__device__ __forceinline__ void unpack2(unsigned long long v, float &lo, float &hi) {
    asm("mov.b64 {%0, %1}, %2;" : "=f"(lo), "=f"(hi) : "l"(v));
}
__device__ __forceinline__ float getf(float4 v, int e) {
    return (e == 0) ? v.x : (e == 1) ? v.y : (e == 2) ? v.z : v.w;
}
__device__ __forceinline__ float hsum16(float v) {
    v += __shfl_xor_sync(0xffffffffu, v, 8);
    v += __shfl_xor_sync(0xffffffffu, v, 4);
    v += __shfl_xor_sync(0xffffffffu, v, 2);
    v += __shfl_xor_sync(0xffffffffu, v, 1);
    return v;
}
__device__ __forceinline__ void cpasync16(uint32_t dst, const void* src) {
    asm volatile("cp.async.cg.shared.global [%0], [%1], 16;" :: "r"(dst), "l"(src));
}
#define CP_COMMIT() asm volatile("cp.async.commit_group;" ::: "memory")
__device__ __forceinline__ void cp_wait3() {
    asm volatile("cp.async.wait_group 3;" ::: "memory");
}
__device__ __forceinline__ void cp_wait4() {
    asm volatile("cp.async.wait_group 4;" ::: "memory");
}

// ---- MLP module: 8 warps x 8 rows = 64 rows/CTA; 12 RHS packed FFMA2 ----
__device__ void mlp_block(const float* __restrict__ Wd,
                          float* __restrict__ out,
                          int l, int dt,
                          char* sm, uint32_t smem_u,
                          int tid, int lane, int wid)
{
    const int rh = lane >> 4;
    const int col = lane & 15;
    const float* wbase = Wd + ((size_t)l * DM + dt * 64 + wid * 8) * IFF;
    const uint32_t wring_u = smem_u + WRING_OFF + wid * WRING_WARP;
    const char* wring = sm + WRING_OFF + wid * WRING_WARP;
    const float4* xg4 = g_xt_mlp + (size_t)l * 11 * 768;

    auto wstep = [&](int s) {
        if (s < 44) {
            const uint32_t dst = wring_u + (s % 5) * 2048 + (rh * 64 + col) * 16;
            const float* src = wbase + (size_t)(rh * 4) * IFF + (s * 16 + col) * 4;
            #pragma unroll
            for (int q = 0; q < 4; q++)
                cpasync16(dst + q * 256, src + (size_t)q * IFF);
        }
        CP_COMMIT();
    };

    float4 pre[3];
    #pragma unroll
    for (int k = 0; k < 3; k++) pre[k] = xg4[tid + k * 256];

    wstep(0); wstep(1); wstep(2); wstep(3);

    unsigned long long acc[4][6];
    #pragma unroll
    for (int q = 0; q < 4; q++)
        #pragma unroll
        for (int p = 0; p < 6; p++) acc[q][p] = 0ull;

    for (int c = 0; c < 11; ++c) {
        float4* xb = reinterpret_cast<float4*>(sm + (c & 1) * XCHUNK_B);
        #pragma unroll
        for (int k = 0; k < 3; k++) xb[tid + k * 256] = pre[k];
        __syncthreads();
        if (c < 10) {
            #pragma unroll
            for (int k = 0; k < 3; k++) pre[k] = xg4[(c + 1) * 768 + tid + k * 256];
        }
        #pragma unroll
        for (int it = 0; it < 4; ++it) {
            const int s = c * 4 + it;
            cp_wait3();
            const char* wq = wring + (s % 5) * 2048;
            float4 w0 = *reinterpret_cast<const float4*>(wq + (rh * 64 + 0 * 16 + col) * 16);
            float4 w1 = *reinterpret_cast<const float4*>(wq + (rh * 64 + 1 * 16 + col) * 16);
            float4 w2 = *reinterpret_cast<const float4*>(wq + (rh * 64 + 2 * 16 + col) * 16);
            float4 w3 = *reinterpret_cast<const float4*>(wq + (rh * 64 + 3 * 16 + col) * 16);
            wstep(s + 4);
            const char* xp = reinterpret_cast<const char*>(xb) + (it * 16 + col) * 16;
            #pragma unroll
            for (int e = 0; e < 4; e++) {
                ulonglong2 x0 = *reinterpret_cast<const ulonglong2*>(xp + (e * 3 + 0) * 1024);
                ulonglong2 x1 = *reinterpret_cast<const ulonglong2*>(xp + (e * 3 + 1) * 1024);
                ulonglong2 x2 = *reinterpret_cast<const ulonglong2*>(xp + (e * 3 + 2) * 1024);
                unsigned long long d0 = fdup(getf(w0, e));
                unsigned long long d1 = fdup(getf(w1, e));
                unsigned long long d2 = fdup(getf(w2, e));
                unsigned long long d3 = fdup(getf(w3, e));
                ffma2(acc[0][0], d0, x0.x); ffma2(acc[0][1], d0, x0.y);
                ffma2(acc[0][2], d0, x1.x); ffma2(acc[0][3], d0, x1.y);
                ffma2(acc[0][4], d0, x2.x); ffma2(acc[0][5], d0, x2.y);
                ffma2(acc[1][0], d1, x0.x); ffma2(acc[1][1], d1, x0.y);
                ffma2(acc[1][2], d1, x1.x); ffma2(acc[1][3], d1, x1.y);
                ffma2(acc[1][4], d1, x2.x); ffma2(acc[1][5], d1, x2.y);
                ffma2(acc[2][0], d2, x0.x); ffma2(acc[2][1], d2, x0.y);
                ffma2(acc[2][2], d2, x1.x); ffma2(acc[2][3], d2, x1.y);
                ffma2(acc[2][4], d2, x2.x); ffma2(acc[2][5], d2, x2.y);
                ffma2(acc[3][0], d3, x0.x); ffma2(acc[3][1], d3, x0.y);
                ffma2(acc[3][2], d3, x1.x); ffma2(acc[3][3], d3, x1.y);
                ffma2(acc[3][4], d3, x2.x); ffma2(acc[3][5], d3, x2.y);
            }
        }
    }

    const int d0w = dt * 64 + wid * 8 + rh * 4;
    const int li = lane & 15;
    #pragma unroll
    for (int q = 0; q < 4; q++)
        #pragma unroll
        for (int pp = 0; pp < 6; pp++) {
            float lo, hi;
            unpack2(acc[q][pp], lo, hi);
            lo = hsum16(lo);
            hi = hsum16(hi);
            if (li == ((q * 6 + pp) & 15)) {
                #pragma unroll
                for (int h = 0; h < 2; h++) {
                    const int j = 2 * pp + h;
                    const int m = j >> 2;
                    const int k = j & 3;
                    const int mod = (m == 0) ? 3 : (m == 1) ? 4 : 6;
                    out[(size_t)((l * 7 + mod) * 8 + 4 + k) * DM + d0w + q] =
                        h ? hi : lo;
                }
            }
        }
}

// ---- Affine module: 8 warps x 8 rows = 64 rows/CTA; 4 RHS packed FFMA2 ----
template <int I>
__device__ void affine_block(const float4* __restrict__ xt,
                             const float* __restrict__ W,
                             float* __restrict__ out,
                             int l, int dt, int mod,
                             char* sm, uint32_t smem_u,
                             int tid, int lane, int wid)
{
    const int COLS = I / 4;
    const int S = COLS / 16;            // 16 (IQO) or 4 (IKV)
    const int rh = lane >> 4;
    const int col = lane & 15;
    const float* wbase = W + ((size_t)l * DM + dt * 64 + wid * 8) * I;
    const uint32_t wring_u = smem_u + WRING_OFF + wid * WRING_WARP;
    const char* wring = sm + WRING_OFF + wid * WRING_WARP;

    // Stage x (e-major, I quads) via cp.async: group A.
    const float4* xs = xt + (size_t)l * I;
    #pragma unroll
    for (int i = tid; i < I; i += 256)
        cpasync16(smem_u + i * 16, xs + i);
    CP_COMMIT();

    auto wstep = [&](int s) {
        if (s < S) {
            const uint32_t dst = wring_u + (s % 5) * 2048 + (rh * 64 + col) * 16;
            const float* src = wbase + (size_t)(rh * 4) * I + (s * 16 + col) * 4;
            #pragma unroll
            for (int q = 0; q < 4; q++)
                cpasync16(dst + q * 256, src + (size_t)q * I);
        }
        CP_COMMIT();
    };
    wstep(0); wstep(1); wstep(2); wstep(3);

    cp_wait4();                 // retire x group A
    __syncthreads();

    unsigned long long acc[4][2];
    #pragma unroll
    for (int q = 0; q < 4; q++) { acc[q][0] = 0ull; acc[q][1] = 0ull; }

    for (int s = 0; s < S; ++s) {
        cp_wait3();
        const char* wq = wring + (s % 5) * 2048;
        float4 w0 = *reinterpret_cast<const float4*>(wq + (rh * 64 + 0 * 16 + col) * 16);
        float4 w1 = *reinterpret_cast<const float4*>(wq + (rh * 64 + 1 * 16 + col) * 16);
        float4 w2 = *reinterpret_cast<const float4*>(wq + (rh * 64 + 2 * 16 + col) * 16);
        float4 w3 = *reinterpret_cast<const float4*>(wq + (rh * 64 + 3 * 16 + col) * 16);
        wstep(s + 4);
        const char* xp = sm + (s * 16 + col) * 16;
        #pragma unroll
        for (int e = 0; e < 4; e++) {
            ulonglong2 xv = *reinterpret_cast<const ulonglong2*>(xp + e * (COLS * 16));
            unsigned long long d0 = fdup(getf(w0, e));
            unsigned long long d1 = fdup(getf(w1, e));
            unsigned long long d2 = fdup(getf(w2, e));
            unsigned long long d3 = fdup(getf(w3, e));
            ffma2(acc[0][0], d0, xv.x); ffma2(acc[0][1], d0, xv.y);
            ffma2(acc[1][0], d1, xv.x); ffma2(acc[1][1], d1, xv.y);
            ffma2(acc[2][0], d2, xv.x); ffma2(acc[2][1], d2, xv.y);
            ffma2(acc[3][0], d3, xv.x); ffma2(acc[3][1], d3, xv.y);
        }
    }

    const int d0w = dt * 64 + wid * 8 + rh * 4;
    const int rowb = (l * 7 + mod) * 8 + 4;
    const int li = lane & 15;
    #pragma unroll
    for (int q = 0; q < 4; q++)
        #pragma unroll
        for (int p = 0; p < 2; p++) {
            float lo, hi;
            unpack2(acc[q][p], lo, hi);
            lo = hsum16(lo);
            hi = hsum16(hi);
            if (li == (q * 4 + 2 * p))
                out[(size_t)(rowb + 2 * p) * DM + d0w + q] = lo;
            if (li == (q * 4 + 2 * p + 1))
                out[(size_t)(rowb + 2 * p + 1) * DM + d0w + q] = hi;
        }
}

__global__ __launch_bounds__(256, 2)
void bse_fused_kernel(const float* __restrict__ residual,
                      const float* __restrict__ Wq,
                      const float* __restrict__ Wk,
                      const float* __restrict__ Wv,
                      const float* __restrict__ Wo,
                      const float* __restrict__ Wd,
                      float* __restrict__ out)
{
    extern __shared__ __align__(16) char sm[];
    const int bid = blockIdx.x;
    const int tid = threadIdx.x;
    const int lane = tid & 31;
    const int wid = tid >> 5;
    const uint32_t smem_u = (uint32_t)__cvta_generic_to_shared(sm);

    if (bid < 512) {
        mlp_block(Wd, out, bid >> 4, bid & 15, sm, smem_u, tid, lane, wid);
    } else if (bid < 1024) {
        const int a = bid - 512;
        affine_block<IQO>(g_xt_q, Wq, out, a >> 4, a & 15, 0, sm, smem_u, tid, lane, wid);
    } else if (bid < 1536) {
        const int a = bid - 1024;
        affine_block<IQO>(g_xt_o, Wo, out, a >> 4, a & 15, 5, sm, smem_u, tid, lane, wid);
    } else if (bid < 2048) {
        const int a = bid - 1536;
        affine_block<IKV>(g_xt_k, Wk, out, a >> 4, a & 15, 1, sm, smem_u, tid, lane, wid);
    } else if (bid < 2560) {
        const int a = bid - 2048;
        affine_block<IKV>(g_xt_v, Wv, out, a >> 4, a & 15, 2, sm, smem_u, tid, lane, wid);
    } else {
        // Residual copy: residual[l,mod,k,:] -> out row (g*8 + k)
        const float4* src = reinterpret_cast<const float4*>(residual);
        float4* dst = reinterpret_cast<float4*>(out);
        const int n = NL * 7 * NK * (DM / 4);          // 229376 float4
        for (int e = (bid - 2560) * 256 + tid; e < n; e += 512 * 256) {
            const int d = e & 255;
            const int k = (e >> 8) & 3;
            const int g = e >> 10;
            dst[(size_t)(g * 8 + k) * 256 + d] = __ldcs(src + e);
        }
    }
}

extern "C" void kernel_launch(void* const* d_in, const int* in_sizes, int n_in,
                              void* d_out, int out_size)
{
    (void)in_sizes; (void)n_in; (void)out_size;
    const float* residual = (const float*)d_in[0];
    const float* cq = (const float*)d_in[1];
    const float* ck = (const float*)d_in[2];
    const float* cv = (const float*)d_in[3];
    const float* co = (const float*)d_in[4];
    const float* cm = (const float*)d_in[5];
    const float* Wq = (const float*)d_in[6];
    const float* Wk = (const float*)d_in[7];
    const float* Wv = (const float*)d_in[8];
    const float* Wo = (const float*)d_in[9];
    const float* Wd = (const float*)d_in[10];
    float* out = (float*)d_out;

    static bool attr_done = false;
    if (!attr_done) {
        cudaFuncSetAttribute(bse_fused_kernel,
                             cudaFuncAttributeMaxDynamicSharedMemorySize, SMEM_BYTES);
        attr_done = true;
    }

    transpose_x_kernel<<<512, 256>>>(cq, ck, cv, co, cm);
    bse_fused_kernel<<<3072, 256, SMEM_BYTES>>>(residual,
                                                Wq, Wk, Wv, Wo, Wd, out);
}

// round 13
// speedup vs baseline: 1.3786x; 1.0051x over previous
#include <cuda_runtime.h>
#include <cstdint>

#define NL 32
#define DM 1024
#define NK 4
#define IQO 1024
#define IKV 256
#define IFF 2816

#define XCHUNK_B 12288                // 768 quads, e-major: ((e*3+p)*64 + cc)*16
#define WRING_OFF (2 * XCHUNK_B)      // 24576
#define WRING_WARP 10240              // 5 slots x 2048 B
#define SMEM_BYTES (WRING_OFF + 8 * WRING_WARP)   // 106496

// -------- transposed x scratch (prologue) --------
// mlp: quad (l*11 + c)*768 + (e*3+p)*64 + ccl   = x[j=4p..4p+3] at elem ((c*64+ccl)*4+e)
// q/o: quad l*1024 + e*256 + cc                 = x[k=0..3] at elem cc*4+e
// k/v: quad l*256  + e*64  + cc
__device__ float4 g_xt_mlp[NL * 11 * 768];
__device__ float4 g_xt_q[NL * 1024];
__device__ float4 g_xt_o[NL * 1024];
__device__ float4 g_xt_k[NL * 256];
__device__ float4 g_xt_v[NL * 256];

#define PCOPY 224

// ======== prologue: tiled transposes (coalesced both sides) + residual copy ==
__global__ __launch_bounds__(256)
void prologue_kernel(const float4* __restrict__ res,
                     const float* __restrict__ cq,
                     const float* __restrict__ ck,
                     const float* __restrict__ cv,
                     const float* __restrict__ co,
                     const float* __restrict__ cm,
                     float4* __restrict__ out)
{
    __shared__ float4 tile[1024];
    float* tf = reinterpret_cast<float*>(tile);
    const int b = blockIdx.x;
    const int tid = threadIdx.x;

    if (b < 352) {
        // MLP tile: (l, c) ; 12 rows x 64 f4 in, 768 e-major quads out
        const int l = b / 11, c = b - l * 11;
        const float4* cm4 = reinterpret_cast<const float4*>(cm) +
                            (size_t)l * 12 * 704 + c * 64;
        #pragma unroll
        for (int k = 0; k < 3; k++) {
            const int idx = tid + k * 256;
            const int j = idx >> 6, ccl = idx & 63;
            float4 v = __ldcs(cm4 + (size_t)j * 704 + ccl);
            const int p = j >> 2, kk = j & 3;
            tf[((0 * 3 + p) * 64 + ccl) * 4 + kk] = v.x;
            tf[((1 * 3 + p) * 64 + ccl) * 4 + kk] = v.y;
            tf[((2 * 3 + p) * 64 + ccl) * 4 + kk] = v.z;
            tf[((3 * 3 + p) * 64 + ccl) * 4 + kk] = v.w;
        }
        __syncthreads();
        float4* dst = g_xt_mlp + (size_t)b * 768;
        #pragma unroll
        for (int k = 0; k < 3; k++) dst[tid + k * 256] = tile[tid + k * 256];
    } else if (b < 416) {
        // q/o tile: one layer each; 4 rows x 256 f4 in, 1024 e-major quads out
        const int t = b - 352, l = t >> 1;
        const float* src = (t & 1) ? co : cq;
        float4* dst = ((t & 1) ? g_xt_o : g_xt_q) + (size_t)l * 1024;
        const float4* s4 = reinterpret_cast<const float4*>(src) + (size_t)l * 4 * 256;
        #pragma unroll
        for (int k = 0; k < 4; k++) {
            const int idx = tid + k * 256;
            const int kr = idx >> 8, cc = idx & 255;
            float4 v = __ldcs(s4 + (size_t)kr * 256 + cc);
            tf[(0 * 256 + cc) * 4 + kr] = v.x;
            tf[(1 * 256 + cc) * 4 + kr] = v.y;
            tf[(2 * 256 + cc) * 4 + kr] = v.z;
            tf[(3 * 256 + cc) * 4 + kr] = v.w;
        }
        __syncthreads();
        #pragma unroll
        for (int k = 0; k < 4; k++) dst[tid + k * 256] = tile[tid + k * 256];
    } else if (b < 480) {
        // k/v tile: one layer each; 4 rows x 64 f4 in, 256 e-major quads out
        const int t = b - 416, l = t >> 1;
        const float* src = (t & 1) ? cv : ck;
        float4* dst = ((t & 1) ? g_xt_v : g_xt_k) + (size_t)l * 256;
        const float4* s4 = reinterpret_cast<const float4*>(src) + (size_t)l * 4 * 64;
        if (tid < 256) {
            const int kr = tid >> 6, cc = tid & 63;
            float4 v = __ldcs(s4 + (size_t)kr * 64 + cc);
            tf[(0 * 64 + cc) * 4 + kr] = v.x;
            tf[(1 * 64 + cc) * 4 + kr] = v.y;
            tf[(2 * 64 + cc) * 4 + kr] = v.z;
            tf[(3 * 64 + cc) * 4 + kr] = v.w;
        }
        __syncthreads();
        if (tid < 256) dst[tid] = tile[tid];
    } else {
        // Residual copy: residual[l,mod,k,:] -> out row (g*8 + k)
        const int n = NL * 7 * NK * (DM / 4);          // 229376 float4
        for (int e = (b - 480) * 256 + tid; e < n; e += PCOPY * 256) {
            const int d = e & 255;
            const int k = (e >> 8) & 3;
            const int g = e >> 10;
            out[(size_t)(g * 8 + k) * 256 + d] = __ldcs(res + e);
        }
    }
}

// -------- helpers --------
__device__ __forceinline__ void ffma2(unsigned long long &d,
                                      unsigned long long a,
                                      unsigned long long b) {
    asm("fma.rn.f32x2 %0, %1, %2, %0;" : "+l"(d) : "l"(a), "l"(b));
}
__device__ __forceinline__ unsigned long long fdup(float f) {
    unsigned long long r;
    asm("mov.b64 %0, {%1, %1};" : "=l"(r) : "f"(f));
    return r;
}
__device__ __forceinline__ void unpack2(unsigned long long v, float &lo, float &hi) {
    asm("mov.b64 {%0, %1}, %2;" : "=f"(lo), "=f"(hi) : "l"(v));
}
__device__ __forceinline__ float getf(float4 v, int e) {
    return (e == 0) ? v.x : (e == 1) ? v.y : (e == 2) ? v.z : v.w;
}
__device__ __forceinline__ float hsum16(float v) {
    v += __shfl_xor_sync(0xffffffffu, v, 8);
    v += __shfl_xor_sync(0xffffffffu, v, 4);
    v += __shfl_xor_sync(0xffffffffu, v, 2);
    v += __shfl_xor_sync(0xffffffffu, v, 1);
    return v;
}
__device__ __forceinline__ void cpasync16(uint32_t dst, const void* src) {
    asm volatile("cp.async.cg.shared.global [%0], [%1], 16;" :: "r"(dst), "l"(src));
}
#define CP_COMMIT() asm volatile("cp.async.commit_group;" ::: "memory")
__device__ __forceinline__ void cp_wait3() {
    asm volatile("cp.async.wait_group 3;" ::: "memory");
}
__device__ __forceinline__ void cp_wait4() {
    asm volatile("cp.async.wait_group 4;" ::: "memory");
}

// ---- MLP module: 8 warps x 8 rows = 64 rows/CTA; 12 RHS packed FFMA2 ----
__device__ void mlp_block(const float* __restrict__ Wd,
                          float* __restrict__ out,
                          int l, int dt,
                          char* sm, uint32_t smem_u,
                          int tid, int lane, int wid)
{
    const int rh = lane >> 4;
    const int col = lane & 15;
    const float* wbase = Wd + ((size_t)l * DM + dt * 64 + wid * 8) * IFF;
    const uint32_t wring_u = smem_u + WRING_OFF + wid * WRING_WARP;
    const char* wring = sm + WRING_OFF + wid * WRING_WARP;
    const float4* xg4 = g_xt_mlp + (size_t)l * 11 * 768;

    auto wstep = [&](int s) {
        if (s < 44) {
            const uint32_t dst = wring_u + (s % 5) * 2048 + (rh * 64 + col) * 16;
            const float* src = wbase + (size_t)(rh * 4) * IFF + (s * 16 + col) * 4;
            #pragma unroll
            for (int q = 0; q < 4; q++)
                cpasync16(dst + q * 256, src + (size_t)q * IFF);
        }
        CP_COMMIT();
    };

    float4 pre[3];
    #pragma unroll
    for (int k = 0; k < 3; k++) pre[k] = xg4[tid + k * 256];

    wstep(0); wstep(1); wstep(2); wstep(3);

    unsigned long long acc[4][6];
    #pragma unroll
    for (int q = 0; q < 4; q++)
        #pragma unroll
        for (int p = 0; p < 6; p++) acc[q][p] = 0ull;

    for (int c = 0; c < 11; ++c) {
        float4* xb = reinterpret_cast<float4*>(sm + (c & 1) * XCHUNK_B);
        #pragma unroll
        for (int k = 0; k < 3; k++) xb[tid + k * 256] = pre[k];
        __syncthreads();
        if (c < 10) {
            #pragma unroll
            for (int k = 0; k < 3; k++) pre[k] = xg4[(c + 1) * 768 + tid + k * 256];
        }
        #pragma unroll
        for (int it = 0; it < 4; ++it) {
            const int s = c * 4 + it;
            cp_wait3();
            const char* wq = wring + (s % 5) * 2048;
            float4 w0 = *reinterpret_cast<const float4*>(wq + (rh * 64 + 0 * 16 + col) * 16);
            float4 w1 = *reinterpret_cast<const float4*>(wq + (rh * 64 + 1 * 16 + col) * 16);
            float4 w2 = *reinterpret_cast<const float4*>(wq + (rh * 64 + 2 * 16 + col) * 16);
            float4 w3 = *reinterpret_cast<const float4*>(wq + (rh * 64 + 3 * 16 + col) * 16);
            wstep(s + 4);
            const char* xp = reinterpret_cast<const char*>(xb) + (it * 16 + col) * 16;
            #pragma unroll
            for (int e = 0; e < 4; e++) {
                ulonglong2 x0 = *reinterpret_cast<const ulonglong2*>(xp + (e * 3 + 0) * 1024);
                ulonglong2 x1 = *reinterpret_cast<const ulonglong2*>(xp + (e * 3 + 1) * 1024);
                ulonglong2 x2 = *reinterpret_cast<const ulonglong2*>(xp + (e * 3 + 2) * 1024);
                unsigned long long d0 = fdup(getf(w0, e));
                unsigned long long d1 = fdup(getf(w1, e));
                unsigned long long d2 = fdup(getf(w2, e));
                unsigned long long d3 = fdup(getf(w3, e));
                ffma2(acc[0][0], d0, x0.x); ffma2(acc[0][1], d0, x0.y);
                ffma2(acc[0][2], d0, x1.x); ffma2(acc[0][3], d0, x1.y);
                ffma2(acc[0][4], d0, x2.x); ffma2(acc[0][5], d0, x2.y);
                ffma2(acc[1][0], d1, x0.x); ffma2(acc[1][1], d1, x0.y);
                ffma2(acc[1][2], d1, x1.x); ffma2(acc[1][3], d1, x1.y);
                ffma2(acc[1][4], d1, x2.x); ffma2(acc[1][5], d1, x2.y);
                ffma2(acc[2][0], d2, x0.x); ffma2(acc[2][1], d2, x0.y);
                ffma2(acc[2][2], d2, x1.x); ffma2(acc[2][3], d2, x1.y);
                ffma2(acc[2][4], d2, x2.x); ffma2(acc[2][5], d2, x2.y);
                ffma2(acc[3][0], d3, x0.x); ffma2(acc[3][1], d3, x0.y);
                ffma2(acc[3][2], d3, x1.x); ffma2(acc[3][3], d3, x1.y);
                ffma2(acc[3][4], d3, x2.x); ffma2(acc[3][5], d3, x2.y);
            }
        }
    }

    const int d0w = dt * 64 + wid * 8 + rh * 4;
    const int li = lane & 15;
    #pragma unroll
    for (int q = 0; q < 4; q++)
        #pragma unroll
        for (int pp = 0; pp < 6; pp++) {
            float lo, hi;
            unpack2(acc[q][pp], lo, hi);
            lo = hsum16(lo);
            hi = hsum16(hi);
            if (li == ((q * 6 + pp) & 15)) {
                #pragma unroll
                for (int h = 0; h < 2; h++) {
                    const int j = 2 * pp + h;
                    const int m = j >> 2;
                    const int k = j & 3;
                    const int mod = (m == 0) ? 3 : (m == 1) ? 4 : 6;
                    out[(size_t)((l * 7 + mod) * 8 + 4 + k) * DM + d0w + q] =
                        h ? hi : lo;
                }
            }
        }
}

// ---- Affine module: 8 warps x 8 rows = 64 rows/CTA; 4 RHS packed FFMA2 ----
template <int I>
__device__ void affine_block(const float4* __restrict__ xt,
                             const float* __restrict__ W,
                             float* __restrict__ out,
                             int l, int dt, int mod,
                             char* sm, uint32_t smem_u,
                             int tid, int lane, int wid)
{
    const int COLS = I / 4;
    const int S = COLS / 16;            // 16 (IQO) or 4 (IKV)
    const int rh = lane >> 4;
    const int col = lane & 15;
    const float* wbase = W + ((size_t)l * DM + dt * 64 + wid * 8) * I;
    const uint32_t wring_u = smem_u + WRING_OFF + wid * WRING_WARP;
    const char* wring = sm + WRING_OFF + wid * WRING_WARP;

    // Stage x (e-major, I quads) via cp.async: group A.
    const float4* xs = xt + (size_t)l * I;
    #pragma unroll
    for (int i = tid; i < I; i += 256)
        cpasync16(smem_u + i * 16, xs + i);
    CP_COMMIT();

    auto wstep = [&](int s) {
        if (s < S) {
            const uint32_t dst = wring_u + (s % 5) * 2048 + (rh * 64 + col) * 16;
            const float* src = wbase + (size_t)(rh * 4) * I + (s * 16 + col) * 4;
            #pragma unroll
            for (int q = 0; q < 4; q++)
                cpasync16(dst + q * 256, src + (size_t)q * I);
        }
        CP_COMMIT();
    };
    wstep(0); wstep(1); wstep(2); wstep(3);

    cp_wait4();                 // retire x group A
    __syncthreads();

    unsigned long long acc[4][2];
    #pragma unroll
    for (int q = 0; q < 4; q++) { acc[q][0] = 0ull; acc[q][1] = 0ull; }

    for (int s = 0; s < S; ++s) {
        cp_wait3();
        const char* wq = wring + (s % 5) * 2048;
        float4 w0 = *reinterpret_cast<const float4*>(wq + (rh * 64 + 0 * 16 + col) * 16);
        float4 w1 = *reinterpret_cast<const float4*>(wq + (rh * 64 + 1 * 16 + col) * 16);
        float4 w2 = *reinterpret_cast<const float4*>(wq + (rh * 64 + 2 * 16 + col) * 16);
        float4 w3 = *reinterpret_cast<const float4*>(wq + (rh * 64 + 3 * 16 + col) * 16);
        wstep(s + 4);
        const char* xp = sm + (s * 16 + col) * 16;
        #pragma unroll
        for (int e = 0; e < 4; e++) {
            ulonglong2 xv = *reinterpret_cast<const ulonglong2*>(xp + e * (COLS * 16));
            unsigned long long d0 = fdup(getf(w0, e));
            unsigned long long d1 = fdup(getf(w1, e));
            unsigned long long d2 = fdup(getf(w2, e));
            unsigned long long d3 = fdup(getf(w3, e));
            ffma2(acc[0][0], d0, xv.x); ffma2(acc[0][1], d0, xv.y);
            ffma2(acc[1][0], d1, xv.x); ffma2(acc[1][1], d1, xv.y);
            ffma2(acc[2][0], d2, xv.x); ffma2(acc[2][1], d2, xv.y);
            ffma2(acc[3][0], d3, xv.x); ffma2(acc[3][1], d3, xv.y);
        }
    }

    const int d0w = dt * 64 + wid * 8 + rh * 4;
    const int rowb = (l * 7 + mod) * 8 + 4;
    const int li = lane & 15;
    #pragma unroll
    for (int q = 0; q < 4; q++)
        #pragma unroll
        for (int p = 0; p < 2; p++) {
            float lo, hi;
            unpack2(acc[q][p], lo, hi);
            lo = hsum16(lo);
            hi = hsum16(hi);
            if (li == (q * 4 + 2 * p))
                out[(size_t)(rowb + 2 * p) * DM + d0w + q] = lo;
            if (li == (q * 4 + 2 * p + 1))
                out[(size_t)(rowb + 2 * p + 1) * DM + d0w + q] = hi;
        }
}

__global__ __launch_bounds__(256, 2)
void bse_fused_kernel(const float* __restrict__ Wq,
                      const float* __restrict__ Wk,
                      const float* __restrict__ Wv,
                      const float* __restrict__ Wo,
                      const float* __restrict__ Wd,
                      float* __restrict__ out)
{
    extern __shared__ __align__(16) char sm[];
    const int bid = blockIdx.x;
    const int tid = threadIdx.x;
    const int lane = tid & 31;
    const int wid = tid >> 5;
    const uint32_t smem_u = (uint32_t)__cvta_generic_to_shared(sm);

    if (bid < 512) {
        mlp_block(Wd, out, bid >> 4, bid & 15, sm, smem_u, tid, lane, wid);
    } else if (bid < 1024) {
        const int a = bid - 512;
        affine_block<IQO>(g_xt_q, Wq, out, a >> 4, a & 15, 0, sm, smem_u, tid, lane, wid);
    } else if (bid < 1536) {
        const int a = bid - 1024;
        affine_block<IQO>(g_xt_o, Wo, out, a >> 4, a & 15, 5, sm, smem_u, tid, lane, wid);
    } else if (bid < 2048) {
        const int a = bid - 1536;
        affine_block<IKV>(g_xt_k, Wk, out, a >> 4, a & 15, 1, sm, smem_u, tid, lane, wid);
    } else {
        const int a = bid - 2048;
        affine_block<IKV>(g_xt_v, Wv, out, a >> 4, a & 15, 2, sm, smem_u, tid, lane, wid);
    }
}

extern "C" void kernel_launch(void* const* d_in, const int* in_sizes, int n_in,
                              void* d_out, int out_size)
{
    (void)in_sizes; (void)n_in; (void)out_size;
    const float* residual = (const float*)d_in[0];
    const float* cq = (const float*)d_in[1];
    const float* ck = (const float*)d_in[2];
    const float* cv = (const float*)d_in[3];
    const float* co = (const float*)d_in[4];
    const float* cm = (const float*)d_in[5];
    const float* Wq = (const float*)d_in[6];
    const float* Wk = (const float*)d_in[7];
    const float* Wv = (const float*)d_in[8];
    const float* Wo = (const float*)d_in[9];
    const float* Wd = (const float*)d_in[10];
    float* out = (float*)d_out;

    static bool attr_done = false;
    if (!attr_done) {
        cudaFuncSetAttribute(bse_fused_kernel,
                             cudaFuncAttributeMaxDynamicSharedMemorySize, SMEM_BYTES);
        attr_done = true;
    }

    prologue_kernel<<<480 + PCOPY, 256>>>(
        reinterpret_cast<const float4*>(residual),
        cq, ck, cv, co, cm, reinterpret_cast<float4*>(out));
    bse_fused_kernel<<<2560, 256, SMEM_BYTES>>>(Wq, Wk, Wv, Wo, Wd, out);
}

// round 14
// speedup vs baseline: 1.3794x; 1.0005x over previous
#include <cuda_runtime.h>
#include <cstdint>

#define NL 32
#define DM 1024
#define NK 4
#define IQO 1024
#define IKV 256
#define IFF 2816

#define XCHUNK_B 12288                // 768 quads, e-major: ((e*3+p)*64 + cc)*16
#define WRING_OFF (2 * XCHUNK_B)      // 24576
#define WRING_WARP 10240              // 5 slots x 2048 B
#define SMEM_BYTES (WRING_OFF + 8 * WRING_WARP)   // 106496
#define NCOPY 128

// -------- transposed MLP x scratch (prologue) --------
// quad (l*11 + c)*768 + (e*3+p)*64 + ccl = x[j=4p..4p+3] at elem ((c*64+ccl)*4+e)
__device__ float4 g_xt_mlp[NL * 11 * 768];

// ======== prologue: MLP tile transpose only (coalesced both sides) ========
__global__ __launch_bounds__(256)
void prologue_kernel(const float* __restrict__ cm)
{
    __shared__ float4 tile[768];
    float* tf = reinterpret_cast<float*>(tile);
    const int b = blockIdx.x;              // 0..351 : (l, c)
    const int tid = threadIdx.x;
    const int l = b / 11, c = b - l * 11;
    const float4* cm4 = reinterpret_cast<const float4*>(cm) +
                        (size_t)l * 12 * 704 + c * 64;
    #pragma unroll
    for (int k = 0; k < 3; k++) {
        const int idx = tid + k * 256;
        const int j = idx >> 6, ccl = idx & 63;
        float4 v = __ldcs(cm4 + (size_t)j * 704 + ccl);
        const int p = j >> 2, kk = j & 3;
        tf[((0 * 3 + p) * 64 + ccl) * 4 + kk] = v.x;
        tf[((1 * 3 + p) * 64 + ccl) * 4 + kk] = v.y;
        tf[((2 * 3 + p) * 64 + ccl) * 4 + kk] = v.z;
        tf[((3 * 3 + p) * 64 + ccl) * 4 + kk] = v.w;
    }
    __syncthreads();
    float4* dst = g_xt_mlp + (size_t)b * 768;
    #pragma unroll
    for (int k = 0; k < 3; k++) dst[tid + k * 256] = tile[tid + k * 256];
}

// -------- helpers --------
__device__ __forceinline__ void ffma2(unsigned long long &d,
                                      unsigned long long a,
                                      unsigned long long b) {
    asm("fma.rn.f32x2 %0, %1, %2, %0;" : "+l"(d) : "l"(a), "l"(b));
}
__device__ __forceinline__ unsigned long long fdup(float f) {
    unsigned long long r;
    asm("mov.b64 %0, {%1, %1};" : "=l"(r) : "f"(f));
    return r;
}
__device__ __forceinline__ void unpack2(unsigned long long v, float &lo, float &hi) {
    asm("mov.b64 {%0, %1}, %2;" : "=f"(lo), "=f"(hi) : "l"(v));
}
__device__ __forceinline__ float getf(float4 v, int e) {
    return (e == 0) ? v.x : (e == 1) ? v.y : (e == 2) ? v.z : v.w;
}
__device__ __forceinline__ float hsum16(float v) {
    v += __shfl_xor_sync(0xffffffffu, v, 8);
    v += __shfl_xor_sync(0xffffffffu, v, 4);
    v += __shfl_xor_sync(0xffffffffu, v, 2);
    v += __shfl_xor_sync(0xffffffffu, v, 1);
    return v;
}
__device__ __forceinline__ void cpasync16(uint32_t dst, const void* src) {
    asm volatile("cp.async.cg.shared.global [%0], [%1], 16;" :: "r"(dst), "l"(src));
}
#define CP_COMMIT() asm volatile("cp.async.commit_group;" ::: "memory")
__device__ __forceinline__ void cp_wait3() {
    asm volatile("cp.async.wait_group 3;" ::: "memory");
}

// ---- MLP module: 8 warps x 8 rows = 64 rows/CTA; 12 RHS packed FFMA2 ----
__device__ void mlp_block(const float* __restrict__ Wd,
                          float* __restrict__ out,
                          int l, int dt,
                          char* sm, uint32_t smem_u,
                          int tid, int lane, int wid)
{
    const int rh = lane >> 4;
    const int col = lane & 15;
    const float* wbase = Wd + ((size_t)l * DM + dt * 64 + wid * 8) * IFF;
    const uint32_t wring_u = smem_u + WRING_OFF + wid * WRING_WARP;
    const char* wring = sm + WRING_OFF + wid * WRING_WARP;
    const float4* xg4 = g_xt_mlp + (size_t)l * 11 * 768;

    auto wstep = [&](int s) {
        if (s < 44) {
            const uint32_t dst = wring_u + (s % 5) * 2048 + (rh * 64 + col) * 16;
            const float* src = wbase + (size_t)(rh * 4) * IFF + (s * 16 + col) * 4;
            #pragma unroll
            for (int q = 0; q < 4; q++)
                cpasync16(dst + q * 256, src + (size_t)q * IFF);
        }
        CP_COMMIT();
    };

    float4 pre[3];
    #pragma unroll
    for (int k = 0; k < 3; k++) pre[k] = xg4[tid + k * 256];

    wstep(0); wstep(1); wstep(2); wstep(3);

    unsigned long long acc[4][6];
    #pragma unroll
    for (int q = 0; q < 4; q++)
        #pragma unroll
        for (int p = 0; p < 6; p++) acc[q][p] = 0ull;

    for (int c = 0; c < 11; ++c) {
        float4* xb = reinterpret_cast<float4*>(sm + (c & 1) * XCHUNK_B);
        #pragma unroll
        for (int k = 0; k < 3; k++) xb[tid + k * 256] = pre[k];
        __syncthreads();
        if (c < 10) {
            #pragma unroll
            for (int k = 0; k < 3; k++) pre[k] = xg4[(c + 1) * 768 + tid + k * 256];
        }
        #pragma unroll
        for (int it = 0; it < 4; ++it) {
            const int s = c * 4 + it;
            cp_wait3();
            const char* wq = wring + (s % 5) * 2048;
            float4 w0 = *reinterpret_cast<const float4*>(wq + (rh * 64 + 0 * 16 + col) * 16);
            float4 w1 = *reinterpret_cast<const float4*>(wq + (rh * 64 + 1 * 16 + col) * 16);
            float4 w2 = *reinterpret_cast<const float4*>(wq + (rh * 64 + 2 * 16 + col) * 16);
            float4 w3 = *reinterpret_cast<const float4*>(wq + (rh * 64 + 3 * 16 + col) * 16);
            wstep(s + 4);
            const char* xp = reinterpret_cast<const char*>(xb) + (it * 16 + col) * 16;
            #pragma unroll
            for (int e = 0; e < 4; e++) {
                ulonglong2 x0 = *reinterpret_cast<const ulonglong2*>(xp + (e * 3 + 0) * 1024);
                ulonglong2 x1 = *reinterpret_cast<const ulonglong2*>(xp + (e * 3 + 1) * 1024);
                ulonglong2 x2 = *reinterpret_cast<const ulonglong2*>(xp + (e * 3 + 2) * 1024);
                unsigned long long d0 = fdup(getf(w0, e));
                unsigned long long d1 = fdup(getf(w1, e));
                unsigned long long d2 = fdup(getf(w2, e));
                unsigned long long d3 = fdup(getf(w3, e));
                ffma2(acc[0][0], d0, x0.x); ffma2(acc[0][1], d0, x0.y);
                ffma2(acc[0][2], d0, x1.x); ffma2(acc[0][3], d0, x1.y);
                ffma2(acc[0][4], d0, x2.x); ffma2(acc[0][5], d0, x2.y);
                ffma2(acc[1][0], d1, x0.x); ffma2(acc[1][1], d1, x0.y);
                ffma2(acc[1][2], d1, x1.x); ffma2(acc[1][3], d1, x1.y);
                ffma2(acc[1][4], d1, x2.x); ffma2(acc[1][5], d1, x2.y);
                ffma2(acc[2][0], d2, x0.x); ffma2(acc[2][1], d2, x0.y);
                ffma2(acc[2][2], d2, x1.x); ffma2(acc[2][3], d2, x1.y);
                ffma2(acc[2][4], d2, x2.x); ffma2(acc[2][5], d2, x2.y);
                ffma2(acc[3][0], d3, x0.x); ffma2(acc[3][1], d3, x0.y);
                ffma2(acc[3][2], d3, x1.x); ffma2(acc[3][3], d3, x1.y);
                ffma2(acc[3][4], d3, x2.x); ffma2(acc[3][5], d3, x2.y);
            }
        }
    }

    const int d0w = dt * 64 + wid * 8 + rh * 4;
    const int li = lane & 15;
    #pragma unroll
    for (int q = 0; q < 4; q++)
        #pragma unroll
        for (int pp = 0; pp < 6; pp++) {
            float lo, hi;
            unpack2(acc[q][pp], lo, hi);
            lo = hsum16(lo);
            hi = hsum16(hi);
            if (li == ((q * 6 + pp) & 15)) {
                #pragma unroll
                for (int h = 0; h < 2; h++) {
                    const int j = 2 * pp + h;
                    const int m = j >> 2;
                    const int k = j & 3;
                    const int mod = (m == 0) ? 3 : (m == 1) ? 4 : 6;
                    out[(size_t)((l * 7 + mod) * 8 + 4 + k) * DM + d0w + q] =
                        h ? hi : lo;
                }
            }
        }
}

// ---- Affine module: 8 warps x 8 rows; in-block x transpose to e-major ----
template <int I>
__device__ void affine_block(const float* __restrict__ xg,
                             const float* __restrict__ W,
                             float* __restrict__ out,
                             int l, int dt, int mod,
                             char* sm, uint32_t smem_u,
                             int tid, int lane, int wid)
{
    const int COLS = I / 4;
    const int S = COLS / 16;            // 16 (IQO) or 4 (IKV)
    const int rh = lane >> 4;
    const int col = lane & 15;
    const float* wbase = W + ((size_t)l * DM + dt * 64 + wid * 8) * I;
    const uint32_t wring_u = smem_u + WRING_OFF + wid * WRING_WARP;
    const char* wring = sm + WRING_OFF + wid * WRING_WARP;

    auto wstep = [&](int s) {
        if (s < S) {
            const uint32_t dst = wring_u + (s % 5) * 2048 + (rh * 64 + col) * 16;
            const float* src = wbase + (size_t)(rh * 4) * I + (s * 16 + col) * 4;
            #pragma unroll
            for (int q = 0; q < 4; q++)
                cpasync16(dst + q * 256, src + (size_t)q * I);
        }
        CP_COMMIT();
    };
    wstep(0); wstep(1); wstep(2); wstep(3);

    // One-time in-block transpose: natural x[k][i] -> e-major smem.
    // smem float ((e*COLS + cc)*4 + kr) = x[kr][cc*4 + e]
    {
        const float4* xn = reinterpret_cast<const float4*>(xg) + (size_t)l * I;
        float* tf = reinterpret_cast<float*>(sm);
        #pragma unroll
        for (int it = 0; it < I / 256; it++) {
            const int idx = tid + it * 256;
            const int kr = idx / COLS, cc = idx % COLS;
            float4 v = __ldcs(xn + (size_t)kr * COLS + cc);
            tf[(0 * COLS + cc) * 4 + kr] = v.x;
            tf[(1 * COLS + cc) * 4 + kr] = v.y;
            tf[(2 * COLS + cc) * 4 + kr] = v.z;
            tf[(3 * COLS + cc) * 4 + kr] = v.w;
        }
    }
    __syncthreads();

    unsigned long long acc[4][2];
    #pragma unroll
    for (int q = 0; q < 4; q++) { acc[q][0] = 0ull; acc[q][1] = 0ull; }

    for (int s = 0; s < S; ++s) {
        cp_wait3();
        const char* wq = wring + (s % 5) * 2048;
        float4 w0 = *reinterpret_cast<const float4*>(wq + (rh * 64 + 0 * 16 + col) * 16);
        float4 w1 = *reinterpret_cast<const float4*>(wq + (rh * 64 + 1 * 16 + col) * 16);
        float4 w2 = *reinterpret_cast<const float4*>(wq + (rh * 64 + 2 * 16 + col) * 16);
        float4 w3 = *reinterpret_cast<const float4*>(wq + (rh * 64 + 3 * 16 + col) * 16);
        wstep(s + 4);
        const char* xp = sm + (s * 16 + col) * 16;
        #pragma unroll
        for (int e = 0; e < 4; e++) {
            ulonglong2 xv = *reinterpret_cast<const ulonglong2*>(xp + e * (COLS * 16));
            unsigned long long d0 = fdup(getf(w0, e));
            unsigned long long d1 = fdup(getf(w1, e));
            unsigned long long d2 = fdup(getf(w2, e));
            unsigned long long d3 = fdup(getf(w3, e));
            ffma2(acc[0][0], d0, xv.x); ffma2(acc[0][1], d0, xv.y);
            ffma2(acc[1][0], d1, xv.x); ffma2(acc[1][1], d1, xv.y);
            ffma2(acc[2][0], d2, xv.x); ffma2(acc[2][1], d2, xv.y);
            ffma2(acc[3][0], d3, xv.x); ffma2(acc[3][1], d3, xv.y);
        }
    }

    const int d0w = dt * 64 + wid * 8 + rh * 4;
    const int rowb = (l * 7 + mod) * 8 + 4;
    const int li = lane & 15;
    #pragma unroll
    for (int q = 0; q < 4; q++)
        #pragma unroll
        for (int p = 0; p < 2; p++) {
            float lo, hi;
            unpack2(acc[q][p], lo, hi);
            lo = hsum16(lo);
            hi = hsum16(hi);
            if (li == (q * 4 + 2 * p))
                out[(size_t)(rowb + 2 * p) * DM + d0w + q] = lo;
            if (li == (q * 4 + 2 * p + 1))
                out[(size_t)(rowb + 2 * p + 1) * DM + d0w + q] = hi;
        }
}

__global__ __launch_bounds__(256, 2)
void bse_fused_kernel(const float* __restrict__ residual,
                      const float* __restrict__ cq,
                      const float* __restrict__ ck,
                      const float* __restrict__ cv,
                      const float* __restrict__ co,
                      const float* __restrict__ Wq,
                      const float* __restrict__ Wk,
                      const float* __restrict__ Wv,
                      const float* __restrict__ Wo,
                      const float* __restrict__ Wd,
                      float* __restrict__ out)
{
    extern __shared__ __align__(16) char sm[];
    const int bid = blockIdx.x;
    const int tid = threadIdx.x;
    const int lane = tid & 31;
    const int wid = tid >> 5;
    const uint32_t smem_u = (uint32_t)__cvta_generic_to_shared(sm);

    if (bid < 512) {
        mlp_block(Wd, out, bid >> 4, bid & 15, sm, smem_u, tid, lane, wid);
    } else if (bid < 1024) {
        const int a = bid - 512;
        affine_block<IQO>(cq, Wq, out, a >> 4, a & 15, 0, sm, smem_u, tid, lane, wid);
    } else if (bid < 1536) {
        const int a = bid - 1024;
        affine_block<IQO>(co, Wo, out, a >> 4, a & 15, 5, sm, smem_u, tid, lane, wid);
    } else if (bid < 2048) {
        const int a = bid - 1536;
        affine_block<IKV>(ck, Wk, out, a >> 4, a & 15, 1, sm, smem_u, tid, lane, wid);
    } else if (bid < 2560) {
        const int a = bid - 2048;
        affine_block<IKV>(cv, Wv, out, a >> 4, a & 15, 2, sm, smem_u, tid, lane, wid);
    } else {
        // Residual copy: residual[l,mod,k,:] -> out row (g*8 + k)
        const float4* src = reinterpret_cast<const float4*>(residual);
        float4* dst = reinterpret_cast<float4*>(out);
        const int n = NL * 7 * NK * (DM / 4);          // 229376 float4
        for (int e = (bid - 2560) * 256 + tid; e < n; e += NCOPY * 256) {
            const int d = e & 255;
            const int k = (e >> 8) & 3;
            const int g = e >> 10;
            dst[(size_t)(g * 8 + k) * 256 + d] = __ldcs(src + e);
        }
    }
}

extern "C" void kernel_launch(void* const* d_in, const int* in_sizes, int n_in,
                              void* d_out, int out_size)
{
    (void)in_sizes; (void)n_in; (void)out_size;
    const float* residual = (const float*)d_in[0];
    const float* cq = (const float*)d_in[1];
    const float* ck = (const float*)d_in[2];
    const float* cv = (const float*)d_in[3];
    const float* co = (const float*)d_in[4];
    const float* cm = (const float*)d_in[5];
    const float* Wq = (const float*)d_in[6];
    const float* Wk = (const float*)d_in[7];
    const float* Wv = (const float*)d_in[8];
    const float* Wo = (const float*)d_in[9];
    const float* Wd = (const float*)d_in[10];
    float* out = (float*)d_out;

    static bool attr_done = false;
    if (!attr_done) {
        cudaFuncSetAttribute(bse_fused_kernel,
                             cudaFuncAttributeMaxDynamicSharedMemorySize, SMEM_BYTES);
        attr_done = true;
    }

    prologue_kernel<<<352, 256>>>(cm);
    bse_fused_kernel<<<2560 + NCOPY, 256, SMEM_BYTES>>>(residual, cq, ck, cv, co,
                                                        Wq, Wk, Wv, Wo, Wd, out);
}